// round 8
// baseline (speedup 1.0000x reference)
#include <cuda_runtime.h>
#include <cuda_bf16.h>
#include <math.h>
#include <stdint.h>

#define Bc 4
#define Lc 2048
#define Dc 512
#define Hc 8
#define HDc 64
#define BL (Bc*Lc)

// ---------------- scratch (device globals; no allocation allowed) ----------
__device__ __nv_bfloat16 g_Qh[Bc*Hc*Lc*HDc];
__device__ __nv_bfloat16 g_Ql[Bc*Hc*Lc*HDc];
__device__ __nv_bfloat16 g_Kh[Bc*Hc*Lc*HDc];
__device__ __nv_bfloat16 g_Kl[Bc*Hc*Lc*HDc];
__device__ __nv_bfloat16 g_Vh[Bc*Hc*Lc*HDc];
__device__ __nv_bfloat16 g_Vl[Bc*Hc*Lc*HDc];
__device__ __nv_bfloat16 g_CXh[BL*Dc];
__device__ __nv_bfloat16 g_CXl[BL*Dc];

// ---------------- helpers ---------------------------------------------------
__device__ __forceinline__ uint32_t smem_u32(const void* p) {
    uint32_t a;
    asm("{ .reg .u64 t; cvta.to.shared.u64 t, %1; cvt.u32.u64 %0, t; }"
        : "=r"(a) : "l"(p));
    return a;
}
__device__ __forceinline__ void ldsm4(uint32_t* r, uint32_t addr) {
    asm volatile("ldmatrix.sync.aligned.m8n8.x4.shared.b16 {%0,%1,%2,%3}, [%4];"
                 : "=r"(r[0]), "=r"(r[1]), "=r"(r[2]), "=r"(r[3]) : "r"(addr));
}
__device__ __forceinline__ void ldsm4t(uint32_t* r, uint32_t addr) {
    asm volatile("ldmatrix.sync.aligned.m8n8.x4.trans.shared.b16 {%0,%1,%2,%3}, [%4];"
                 : "=r"(r[0]), "=r"(r[1]), "=r"(r[2]), "=r"(r[3]) : "r"(addr));
}
__device__ __forceinline__ void mma16816(float* d, const uint32_t* a,
                                         uint32_t b0, uint32_t b1) {
    asm volatile("mma.sync.aligned.m16n8k16.row.col.f32.bf16.bf16.f32 "
                 "{%0,%1,%2,%3}, {%4,%5,%6,%7}, {%8,%9}, {%0,%1,%2,%3};"
                 : "+f"(d[0]), "+f"(d[1]), "+f"(d[2]), "+f"(d[3])
                 : "r"(a[0]), "r"(a[1]), "r"(a[2]), "r"(a[3]), "r"(b0), "r"(b1));
}
__device__ __forceinline__ uint32_t packbf2(float lo, float hi) {
    __nv_bfloat162 v = __floats2bfloat162_rn(lo, hi);
    return *(uint32_t*)&v;
}
__device__ __forceinline__ void cpasync16(uint32_t s, const void* g) {
    asm volatile("cp.async.cg.shared.global [%0], [%1], 16;" :: "r"(s), "l"(g) : "memory");
}
__device__ __forceinline__ void cp_commit() {
    asm volatile("cp.async.commit_group;" ::: "memory");
}
__device__ __forceinline__ void cp_wait1() {
    asm volatile("cp.async.wait_group 1;" ::: "memory");
}
// convert 8 fp32 (two float4) -> hi uint4 + lo uint4 (bf16x2 lanes)
__device__ __forceinline__ void split8(const float4 v0, const float4 v1,
                                       uint4& hi, uint4& lo) {
    hi.x = packbf2(v0.x, v0.y); hi.y = packbf2(v0.z, v0.w);
    hi.z = packbf2(v1.x, v1.y); hi.w = packbf2(v1.z, v1.w);
    __nv_bfloat162 h;
    h = *(__nv_bfloat162*)&hi.x;
    lo.x = packbf2(v0.x - __bfloat162float(h.x), v0.y - __bfloat162float(h.y));
    h = *(__nv_bfloat162*)&hi.y;
    lo.y = packbf2(v0.z - __bfloat162float(h.x), v0.w - __bfloat162float(h.y));
    h = *(__nv_bfloat162*)&hi.z;
    lo.z = packbf2(v1.x - __bfloat162float(h.x), v1.y - __bfloat162float(h.y));
    h = *(__nv_bfloat162*)&hi.w;
    lo.w = packbf2(v1.z - __bfloat162float(h.x), v1.w - __bfloat162float(h.y));
}

// ---------------------------------------------------------------------------
// Warp-MMA GEMM: out = A @ W^T + bias, fp32 accuracy via 3 hi/lo passes.
// MODE 1 (projection): A fp32 [8192,512], out = bf16 hi/lo in [B,H,L,HD].
// MODE 0 (output proj): A bf16 hi/lo [8192,512], out fp32 [8192,512].
// W always fp32 [512,512]; converted in the loader.
// Block 256 thr (8 warps), tile 128x64, warp 32x32, BK=64.
// ---------------------------------------------------------------------------
#define GSTR 144  // smem row stride bytes (64 bf16 = 128B + 16 pad)
template<int MODE>
__global__ void __launch_bounds__(256, 2) gemm_mma(
    const float* __restrict__ Afp,
    const __nv_bfloat16* __restrict__ Ah, const __nv_bfloat16* __restrict__ Al,
    const float* __restrict__ W,
    const float* __restrict__ bias, float* __restrict__ out,
    __nv_bfloat16* __restrict__ outh, __nv_bfloat16* __restrict__ outl) {
    extern __shared__ char smem[];
    const uint32_t sb = smem_u32(smem);
    const int t = threadIdx.x, lane = t & 31, wid = t >> 5;
    const int wm = wid & 3, wn = wid >> 2;
    const int row0 = blockIdx.y * 128, col0 = blockIdx.x * 64;
    const uint32_t SAH = 0, SAL = 18432, SBH = 36864, SBL = 46080;

    float d[2][4][4];
#pragma unroll
    for (int i = 0; i < 2; i++)
#pragma unroll
        for (int j = 0; j < 4; j++)
#pragma unroll
            for (int e = 0; e < 4; e++) d[i][j][e] = 0.f;

    float4 va[4][2];
    uint4 ra_h[4], ra_l[4];
    float4 vb[2][2];

    auto gload = [&](int kc) {
        const int k0 = kc * 64;
#pragma unroll
        for (int i = 0; i < 4; i++) {
            int idx = i * 256 + t, r = idx >> 3, ce = (idx & 7) * 8;
            if (MODE == 1) {
                const float4* src = (const float4*)(Afp + (size_t)(row0 + r) * 512 + k0 + ce);
                va[i][0] = src[0]; va[i][1] = src[1];
            } else {
                size_t g = (size_t)(row0 + r) * 512 + k0 + ce;
                ra_h[i] = *(const uint4*)(Ah + g);
                ra_l[i] = *(const uint4*)(Al + g);
            }
        }
#pragma unroll
        for (int i = 0; i < 2; i++) {
            int idx = i * 256 + t, r = idx >> 3, ce = (idx & 7) * 8;
            const float4* src = (const float4*)(W + (size_t)(col0 + r) * 512 + k0 + ce);
            vb[i][0] = src[0]; vb[i][1] = src[1];
        }
    };
    auto sstore = [&]() {
#pragma unroll
        for (int i = 0; i < 4; i++) {
            int idx = i * 256 + t, r = idx >> 3, cb = (idx & 7) * 16;
            uint4 hi, lo;
            if (MODE == 1) split8(va[i][0], va[i][1], hi, lo);
            else { hi = ra_h[i]; lo = ra_l[i]; }
            *(uint4*)(smem + SAH + r * GSTR + cb) = hi;
            *(uint4*)(smem + SAL + r * GSTR + cb) = lo;
        }
#pragma unroll
        for (int i = 0; i < 2; i++) {
            int idx = i * 256 + t, r = idx >> 3, cb = (idx & 7) * 16;
            uint4 hi, lo;
            split8(vb[i][0], vb[i][1], hi, lo);
            *(uint4*)(smem + SBH + r * GSTR + cb) = hi;
            *(uint4*)(smem + SBL + r * GSTR + cb) = lo;
        }
    };

    gload(0);
    for (int c = 0; c < 8; c++) {
        __syncthreads();
        sstore();
        __syncthreads();
        if (c < 7) gload(c + 1);
#pragma unroll
        for (int pass = 0; pass < 3; pass++) {
            uint32_t abase = sb + (pass == 1 ? SAL : SAH);
            uint32_t bbase = sb + (pass == 2 ? SBL : SBH);
#pragma unroll
            for (int ks = 0; ks < 4; ks++) {
                uint32_t af[2][4], bf[2][4];
#pragma unroll
                for (int mt = 0; mt < 2; mt++)
                    ldsm4(af[mt], abase + (wm * 32 + mt * 16 + (lane & 15)) * GSTR
                                  + ks * 32 + (lane >> 4) * 16);
#pragma unroll
                for (int bp = 0; bp < 2; bp++)
                    ldsm4(bf[bp], bbase + (wn * 32 + bp * 16 + (lane & 15)) * GSTR
                                  + ks * 32 + (lane >> 4) * 16);
#pragma unroll
                for (int mt = 0; mt < 2; mt++)
#pragma unroll
                    for (int nt = 0; nt < 4; nt++)
                        mma16816(d[mt][nt], af[mt], bf[nt >> 1][nt & 1], bf[nt >> 1][(nt & 1) + 2]);
            }
        }
    }

    // epilogue
#pragma unroll
    for (int mt = 0; mt < 2; mt++) {
        int r1 = row0 + wm * 32 + mt * 16 + (lane >> 2);
#pragma unroll
        for (int nt = 0; nt < 4; nt++) {
            int cc = col0 + wn * 32 + nt * 8 + (lane & 3) * 2;
            float b0 = bias[cc], b1 = bias[cc + 1];
            float v00 = d[mt][nt][0] + b0, v01 = d[mt][nt][1] + b1;
            float v10 = d[mt][nt][2] + b0, v11 = d[mt][nt][3] + b1;
            if (MODE == 0) {
                *(float2*)(out + (size_t)r1 * 512 + cc) = make_float2(v00, v01);
                *(float2*)(out + (size_t)(r1 + 8) * 512 + cc) = make_float2(v10, v11);
            } else {
                int hd = cc - col0;
#pragma unroll
                for (int rr = 0; rr < 2; rr++) {
                    int r = r1 + rr * 8;
                    float va0 = rr ? v10 : v00, va1 = rr ? v11 : v01;
                    int b = r >> 11, l = r & 2047;
                    size_t idx = (((size_t)(b * Hc + blockIdx.x)) * Lc + l) * HDc + hd;
                    __nv_bfloat16 ha = __float2bfloat16(va0), hb = __float2bfloat16(va1);
                    *(__nv_bfloat162*)(outh + idx) = __halves2bfloat162(ha, hb);
                    *(__nv_bfloat162*)(outl + idx) = __halves2bfloat162(
                        __float2bfloat16(va0 - __bfloat162float(ha)),
                        __float2bfloat16(va1 - __bfloat162float(hb)));
                }
            }
        }
    }
}

// ---------------------------------------------------------------------------
// Warp-MMA causal flash attention, cp.async double-buffered K/V.
// Grid (16, H, B), block 256 (8 warps). 128-query tile; warp w owns rows
// w*16..+15. K/V tiles 64-wide, 2 smem stages. Output bf16 hi/lo ctx [B,L,D].
// __launch_bounds__(256,2): cap regs at 128 so 2 CTAs/SM are resident.
// ---------------------------------------------------------------------------
__global__ void __launch_bounds__(256, 2) flash_mma() {
    extern __shared__ char smem[];
    const uint32_t sb = smem_u32(smem);
    const int t = threadIdx.x, lane = t & 31, w = t >> 5;
    const int qt = 15 - blockIdx.x;  // heavy tiles first
    const int h = blockIdx.y, b = blockIdx.z;
    const size_t base = ((size_t)(b * Hc + h)) * Lc * HDc;
    const uint32_t SQH = 0, SQL = 18432, SST = 36864, STSZ = 36864;
    const uint32_t OKL = 9216, OVH = 18432, OVL = 27648;

    const int njt = 2 * qt + 2;

    // async prefetch of K/V stage
    auto pf = [&](int jt, int st) {
        uint32_t dstb = sb + SST + st * STSZ;
#pragma unroll
        for (int i = 0; i < 2; i++) {
            int idx = i * 256 + t, r = idx >> 3, cb = (idx & 7) * 16, ce = (idx & 7) * 8;
            size_t g = base + (size_t)(jt * 64 + r) * HDc + ce;
            uint32_t d0 = dstb + r * GSTR + cb;
            cpasync16(d0,        g_Kh + g);
            cpasync16(d0 + OKL,  g_Kl + g);
            cpasync16(d0 + OVH,  g_Vh + g);
            cpasync16(d0 + OVL,  g_Vl + g);
        }
    };

    // kick off stage 0 before the Q-tile load (overlap)
    pf(0, 0);
    cp_commit();

    // load Q tile (128 rows x 64 bf16, hi+lo)
#pragma unroll
    for (int i = 0; i < 4; i++) {
        int idx = i * 256 + t, r = idx >> 3, cb = (idx & 7) * 16, ce = (idx & 7) * 8;
        size_t g = base + (size_t)(qt * 128 + r) * HDc + ce;
        *(uint4*)(smem + SQH + r * GSTR + cb) = *(const uint4*)(g_Qh + g);
        *(uint4*)(smem + SQL + r * GSTR + cb) = *(const uint4*)(g_Ql + g);
    }
    __syncthreads();

    uint32_t qfh[4][4], qfl[4][4];
#pragma unroll
    for (int ks = 0; ks < 4; ks++) {
        uint32_t a = (w * 16 + (lane & 15)) * GSTR + ks * 32 + (lane >> 4) * 16;
        ldsm4(qfh[ks], sb + SQH + a);
        ldsm4(qfl[ks], sb + SQL + a);
    }

    float o[8][4];
#pragma unroll
    for (int i = 0; i < 8; i++)
#pragma unroll
        for (int e = 0; e < 4; e++) o[i][e] = 0.f;
    float m0 = -1e30f, m1 = -1e30f, l0 = 0.f, l1 = 0.f;
    const float scale = 0.125f;
    const int qlo = qt * 128 + w * 16;

    for (int jt = 0; jt < njt; jt++) {
        // prefetch next stage while computing this one
        if (jt + 1 < njt) pf(jt + 1, (jt + 1) & 1);
        cp_commit();
        cp_wait1();            // stage jt resident
        __syncthreads();       // visible to all warps; prior compute drained

        const int J0 = jt * 64;
        const uint32_t stb = sb + SST + (jt & 1) * STSZ;

        if (J0 <= qlo + 15) {
            // ---- S = Q K^T (3 passes) ----
            float s[8][4];
#pragma unroll
            for (int i = 0; i < 8; i++)
#pragma unroll
                for (int e = 0; e < 4; e++) s[i][e] = 0.f;
#pragma unroll
            for (int pass = 0; pass < 3; pass++) {
                const uint32_t (*af)[4] = (pass == 1) ? qfl : qfh;
                uint32_t bbase = stb + ((pass == 2) ? OKL : 0);
#pragma unroll
                for (int ks = 0; ks < 4; ks++) {
#pragma unroll
                    for (int bp = 0; bp < 4; bp++) {
                        uint32_t bf[4];
                        ldsm4(bf, bbase + (bp * 16 + (lane & 15)) * GSTR + ks * 32 + (lane >> 4) * 16);
                        mma16816(s[bp * 2],     af[ks], bf[0], bf[2]);
                        mma16816(s[bp * 2 + 1], af[ks], bf[1], bf[3]);
                    }
                }
            }

            // ---- scale + causal mask ----
            if (J0 + 63 > qlo) {
                int q0 = qlo + (lane >> 2);
#pragma unroll
                for (int nt = 0; nt < 8; nt++) {
                    int kc = J0 + nt * 8 + (lane & 3) * 2;
                    s[nt][0] = (kc     <= q0)     ? s[nt][0] * scale : -1e30f;
                    s[nt][1] = (kc + 1 <= q0)     ? s[nt][1] * scale : -1e30f;
                    s[nt][2] = (kc     <= q0 + 8) ? s[nt][2] * scale : -1e30f;
                    s[nt][3] = (kc + 1 <= q0 + 8) ? s[nt][3] * scale : -1e30f;
                }
            } else {
#pragma unroll
                for (int nt = 0; nt < 8; nt++)
#pragma unroll
                    for (int e = 0; e < 4; e++) s[nt][e] *= scale;
            }

            // ---- online softmax ----
            float a0 = -1e30f, a1 = -1e30f;
#pragma unroll
            for (int nt = 0; nt < 8; nt++) {
                a0 = fmaxf(a0, fmaxf(s[nt][0], s[nt][1]));
                a1 = fmaxf(a1, fmaxf(s[nt][2], s[nt][3]));
            }
            a0 = fmaxf(a0, __shfl_xor_sync(0xffffffffu, a0, 1));
            a0 = fmaxf(a0, __shfl_xor_sync(0xffffffffu, a0, 2));
            a1 = fmaxf(a1, __shfl_xor_sync(0xffffffffu, a1, 1));
            a1 = fmaxf(a1, __shfl_xor_sync(0xffffffffu, a1, 2));
            float n0 = fmaxf(m0, a0), n1 = fmaxf(m1, a1);
            float c0 = __expf(m0 - n0), c1 = __expf(m1 - n1);
            m0 = n0; m1 = n1; l0 *= c0; l1 *= c1;
#pragma unroll
            for (int nt = 0; nt < 8; nt++) {
                o[nt][0] *= c0; o[nt][1] *= c0; o[nt][2] *= c1; o[nt][3] *= c1;
            }

            // ---- P = exp(S - m); PV accumulation ----
#pragma unroll
            for (int ks = 0; ks < 4; ks++) {
                float p[8];
                p[0] = __expf(s[2 * ks][0] - n0);     p[1] = __expf(s[2 * ks][1] - n0);
                p[2] = __expf(s[2 * ks][2] - n1);     p[3] = __expf(s[2 * ks][3] - n1);
                p[4] = __expf(s[2 * ks + 1][0] - n0); p[5] = __expf(s[2 * ks + 1][1] - n0);
                p[6] = __expf(s[2 * ks + 1][2] - n1); p[7] = __expf(s[2 * ks + 1][3] - n1);
                l0 += p[0] + p[1] + p[4] + p[5];
                l1 += p[2] + p[3] + p[6] + p[7];
                uint32_t ph[4], pl[4];
#pragma unroll
                for (int j = 0; j < 4; j++) {
                    float e0 = p[j * 2], e1 = p[j * 2 + 1];
                    ph[j] = packbf2(e0, e1);
                    __nv_bfloat162 hv = *(__nv_bfloat162*)&ph[j];
                    pl[j] = packbf2(e0 - __bfloat162float(hv.x), e1 - __bfloat162float(hv.y));
                }
#pragma unroll
                for (int np = 0; np < 4; np++) {
                    uint32_t a = stb + OVH + (ks * 16 + (lane & 15)) * GSTR + np * 32 + (lane >> 4) * 16;
                    uint32_t vh[4], vl[4];
                    ldsm4t(vh, a);
                    ldsm4t(vl, a + (OVL - OVH));
                    mma16816(o[np * 2],     ph, vh[0], vh[1]);
                    mma16816(o[np * 2 + 1], ph, vh[2], vh[3]);
                    mma16816(o[np * 2],     pl, vh[0], vh[1]);
                    mma16816(o[np * 2 + 1], pl, vh[2], vh[3]);
                    mma16816(o[np * 2],     ph, vl[0], vl[1]);
                    mma16816(o[np * 2 + 1], ph, vl[2], vl[3]);
                }
            }
        }
        __syncthreads();  // all warps done with stage jt before it is overwritten
    }

    // ---- finalize: write bf16 hi/lo ctx in [B,L,D] ----
    l0 += __shfl_xor_sync(0xffffffffu, l0, 1);
    l0 += __shfl_xor_sync(0xffffffffu, l0, 2);
    l1 += __shfl_xor_sync(0xffffffffu, l1, 1);
    l1 += __shfl_xor_sync(0xffffffffu, l1, 2);
    float i0 = 1.f / l0, i1 = 1.f / l1;
    int qrow = qt * 128 + w * 16 + (lane >> 2);
    size_t r0 = (size_t)b * Lc + qrow;
#pragma unroll
    for (int nt = 0; nt < 8; nt++) {
        int cc = h * HDc + nt * 8 + (lane & 3) * 2;
#pragma unroll
        for (int rr = 0; rr < 2; rr++) {
            float va0 = (rr ? o[nt][2] * i1 : o[nt][0] * i0);
            float va1 = (rr ? o[nt][3] * i1 : o[nt][1] * i0);
            size_t idx = (r0 + rr * 8) * Dc + cc;
            __nv_bfloat16 ha = __float2bfloat16(va0), hb = __float2bfloat16(va1);
            *(__nv_bfloat162*)(g_CXh + idx) = __halves2bfloat162(ha, hb);
            *(__nv_bfloat162*)(g_CXl + idx) = __halves2bfloat162(
                __float2bfloat16(va0 - __bfloat162float(ha)),
                __float2bfloat16(va1 - __bfloat162float(hb)));
        }
    }
}

// ---------------------------------------------------------------------------
extern "C" void kernel_launch(void* const* d_in, const int* in_sizes, int n_in,
                              void* d_out, int out_size) {
    const float* q  = (const float*)d_in[0];
    const float* k  = (const float*)d_in[1];
    const float* v  = (const float*)d_in[2];
    const float* Wq = (const float*)d_in[4];
    const float* bq = (const float*)d_in[5];
    const float* Wk = (const float*)d_in[6];
    const float* bk = (const float*)d_in[7];
    const float* Wv = (const float*)d_in[8];
    const float* bv = (const float*)d_in[9];
    const float* Wo = (const float*)d_in[10];
    const float* bo = (const float*)d_in[11];
    float* out = (float*)d_out;

    __nv_bfloat16 *Qh, *Ql, *Kh, *Kl, *Vh, *Vl, *CXh, *CXl;
    cudaGetSymbolAddress((void**)&Qh, g_Qh);
    cudaGetSymbolAddress((void**)&Ql, g_Ql);
    cudaGetSymbolAddress((void**)&Kh, g_Kh);
    cudaGetSymbolAddress((void**)&Kl, g_Kl);
    cudaGetSymbolAddress((void**)&Vh, g_Vh);
    cudaGetSymbolAddress((void**)&Vl, g_Vl);
    cudaGetSymbolAddress((void**)&CXh, g_CXh);
    cudaGetSymbolAddress((void**)&CXl, g_CXl);

    const int gsmem = 55296;
    const int fsmem = 36864 + 2 * 36864;  // 110592
    cudaFuncSetAttribute(gemm_mma<0>, cudaFuncAttributeMaxDynamicSharedMemorySize, gsmem);
    cudaFuncSetAttribute(gemm_mma<1>, cudaFuncAttributeMaxDynamicSharedMemorySize, gsmem);
    cudaFuncSetAttribute(flash_mma, cudaFuncAttributeMaxDynamicSharedMemorySize, fsmem);

    dim3 grd_gemm(Dc / 64, BL / 128);  // 8 x 64

    gemm_mma<1><<<grd_gemm, 256, gsmem>>>(q, nullptr, nullptr, Wq, bq, nullptr, Qh, Ql);
    gemm_mma<1><<<grd_gemm, 256, gsmem>>>(k, nullptr, nullptr, Wk, bk, nullptr, Kh, Kl);
    gemm_mma<1><<<grd_gemm, 256, gsmem>>>(v, nullptr, nullptr, Wv, bv, nullptr, Vh, Vl);

    dim3 grd_fa(Lc / 128, Hc, Bc);     // 16 x 8 x 4
    flash_mma<<<grd_fa, 256, fsmem>>>();

    gemm_mma<0><<<grd_gemm, 256, gsmem>>>(nullptr, CXh, CXl, Wo, bo, out, nullptr, nullptr);
}

// round 9
// speedup vs baseline: 1.2182x; 1.2182x over previous
#include <cuda_runtime.h>
#include <cuda_bf16.h>
#include <math.h>
#include <stdint.h>

#define Bc 4
#define Lc 2048
#define Dc 512
#define Hc 8
#define HDc 64
#define BL (Bc*Lc)

// ---------------- scratch (device globals; no allocation allowed) ----------
__device__ __nv_bfloat16 g_Qh[Bc*Hc*Lc*HDc];
__device__ __nv_bfloat16 g_Ql[Bc*Hc*Lc*HDc];
__device__ __nv_bfloat16 g_Kh[Bc*Hc*Lc*HDc];
__device__ __nv_bfloat16 g_Kl[Bc*Hc*Lc*HDc];
__device__ __nv_bfloat16 g_Vh[Bc*Hc*Lc*HDc];
__device__ __nv_bfloat16 g_Vl[Bc*Hc*Lc*HDc];
__device__ __nv_bfloat16 g_CXh[BL*Dc];
__device__ __nv_bfloat16 g_CXl[BL*Dc];

// ---------------- helpers ---------------------------------------------------
__device__ __forceinline__ uint32_t smem_u32(const void* p) {
    uint32_t a;
    asm("{ .reg .u64 t; cvta.to.shared.u64 t, %1; cvt.u32.u64 %0, t; }"
        : "=r"(a) : "l"(p));
    return a;
}
__device__ __forceinline__ void ldsm4(uint32_t* r, uint32_t addr) {
    asm volatile("ldmatrix.sync.aligned.m8n8.x4.shared.b16 {%0,%1,%2,%3}, [%4];"
                 : "=r"(r[0]), "=r"(r[1]), "=r"(r[2]), "=r"(r[3]) : "r"(addr));
}
__device__ __forceinline__ void ldsm4t(uint32_t* r, uint32_t addr) {
    asm volatile("ldmatrix.sync.aligned.m8n8.x4.trans.shared.b16 {%0,%1,%2,%3}, [%4];"
                 : "=r"(r[0]), "=r"(r[1]), "=r"(r[2]), "=r"(r[3]) : "r"(addr));
}
__device__ __forceinline__ void mma16816(float* d, const uint32_t* a,
                                         uint32_t b0, uint32_t b1) {
    asm volatile("mma.sync.aligned.m16n8k16.row.col.f32.bf16.bf16.f32 "
                 "{%0,%1,%2,%3}, {%4,%5,%6,%7}, {%8,%9}, {%0,%1,%2,%3};"
                 : "+f"(d[0]), "+f"(d[1]), "+f"(d[2]), "+f"(d[3])
                 : "r"(a[0]), "r"(a[1]), "r"(a[2]), "r"(a[3]), "r"(b0), "r"(b1));
}
__device__ __forceinline__ uint32_t packbf2(float lo, float hi) {
    __nv_bfloat162 v = __floats2bfloat162_rn(lo, hi);
    return *(uint32_t*)&v;
}
__device__ __forceinline__ void cpasync16(uint32_t s, const void* g) {
    asm volatile("cp.async.cg.shared.global [%0], [%1], 16;" :: "r"(s), "l"(g) : "memory");
}
__device__ __forceinline__ void cp_commit() {
    asm volatile("cp.async.commit_group;" ::: "memory");
}
__device__ __forceinline__ void cp_wait1() {
    asm volatile("cp.async.wait_group 1;" ::: "memory");
}
// convert 8 fp32 (two float4) -> hi uint4 + lo uint4 (bf16x2 lanes)
__device__ __forceinline__ void split8(const float4 v0, const float4 v1,
                                       uint4& hi, uint4& lo) {
    hi.x = packbf2(v0.x, v0.y); hi.y = packbf2(v0.z, v0.w);
    hi.z = packbf2(v1.x, v1.y); hi.w = packbf2(v1.z, v1.w);
    __nv_bfloat162 h;
    h = *(__nv_bfloat162*)&hi.x;
    lo.x = packbf2(v0.x - __bfloat162float(h.x), v0.y - __bfloat162float(h.y));
    h = *(__nv_bfloat162*)&hi.y;
    lo.y = packbf2(v0.z - __bfloat162float(h.x), v0.w - __bfloat162float(h.y));
    h = *(__nv_bfloat162*)&hi.z;
    lo.z = packbf2(v1.x - __bfloat162float(h.x), v1.y - __bfloat162float(h.y));
    h = *(__nv_bfloat162*)&hi.w;
    lo.w = packbf2(v1.z - __bfloat162float(h.x), v1.w - __bfloat162float(h.y));
}

// ---------------------------------------------------------------------------
// Warp-MMA GEMM: out = A @ W^T + bias, fp32 accuracy via 3 hi/lo passes.
// MODE 1 (projection): A fp32 [8192,512], out = bf16 hi/lo in [B,H,L,HD].
// MODE 0 (output proj): A bf16 hi/lo [8192,512], out fp32 [8192,512].
// Inner loop loads each fragment ONCE (ah/al/bh/bl resident): 32 LDSM per
// 96 HMMA per chunk. No min-blocks clause: natural regs, 1 CTA/SM.
// ---------------------------------------------------------------------------
#define GSTR 144  // smem row stride bytes (64 bf16 = 128B + 16 pad)
template<int MODE>
__global__ void __launch_bounds__(256) gemm_mma(
    const float* __restrict__ Afp,
    const __nv_bfloat16* __restrict__ Ah, const __nv_bfloat16* __restrict__ Al,
    const float* __restrict__ W,
    const float* __restrict__ bias, float* __restrict__ out,
    __nv_bfloat16* __restrict__ outh, __nv_bfloat16* __restrict__ outl) {
    extern __shared__ char smem[];
    const uint32_t sb = smem_u32(smem);
    const int t = threadIdx.x, lane = t & 31, wid = t >> 5;
    const int wm = wid & 3, wn = wid >> 2;
    const int row0 = blockIdx.y * 128, col0 = blockIdx.x * 64;
    const uint32_t SAH = 0, SAL = 18432, SBH = 36864, SBL = 46080;

    float d[2][4][4];
#pragma unroll
    for (int i = 0; i < 2; i++)
#pragma unroll
        for (int j = 0; j < 4; j++)
#pragma unroll
            for (int e = 0; e < 4; e++) d[i][j][e] = 0.f;

    float4 va[4][2];
    uint4 ra_h[4], ra_l[4];
    float4 vb[2][2];

    auto gload = [&](int kc) {
        const int k0 = kc * 64;
#pragma unroll
        for (int i = 0; i < 4; i++) {
            int idx = i * 256 + t, r = idx >> 3, ce = (idx & 7) * 8;
            if (MODE == 1) {
                const float4* src = (const float4*)(Afp + (size_t)(row0 + r) * 512 + k0 + ce);
                va[i][0] = src[0]; va[i][1] = src[1];
            } else {
                size_t g = (size_t)(row0 + r) * 512 + k0 + ce;
                ra_h[i] = *(const uint4*)(Ah + g);
                ra_l[i] = *(const uint4*)(Al + g);
            }
        }
#pragma unroll
        for (int i = 0; i < 2; i++) {
            int idx = i * 256 + t, r = idx >> 3, ce = (idx & 7) * 8;
            const float4* src = (const float4*)(W + (size_t)(col0 + r) * 512 + k0 + ce);
            vb[i][0] = src[0]; vb[i][1] = src[1];
        }
    };
    auto sstore = [&]() {
#pragma unroll
        for (int i = 0; i < 4; i++) {
            int idx = i * 256 + t, r = idx >> 3, cb = (idx & 7) * 16;
            uint4 hi, lo;
            if (MODE == 1) split8(va[i][0], va[i][1], hi, lo);
            else { hi = ra_h[i]; lo = ra_l[i]; }
            *(uint4*)(smem + SAH + r * GSTR + cb) = hi;
            *(uint4*)(smem + SAL + r * GSTR + cb) = lo;
        }
#pragma unroll
        for (int i = 0; i < 2; i++) {
            int idx = i * 256 + t, r = idx >> 3, cb = (idx & 7) * 16;
            uint4 hi, lo;
            split8(vb[i][0], vb[i][1], hi, lo);
            *(uint4*)(smem + SBH + r * GSTR + cb) = hi;
            *(uint4*)(smem + SBL + r * GSTR + cb) = lo;
        }
    };

    gload(0);
    for (int c = 0; c < 8; c++) {
        __syncthreads();
        sstore();
        __syncthreads();
        if (c < 7) gload(c + 1);
        // fragment-resident 3-pass: each fragment loaded once
#pragma unroll
        for (int ks = 0; ks < 4; ks++) {
            uint32_t ah[2][4], al[2][4], bh[2][4], bl[2][4];
            uint32_t aoff = (wm * 32 + (lane & 15)) * GSTR + ks * 32 + (lane >> 4) * 16;
            uint32_t boff = (wn * 32 + (lane & 15)) * GSTR + ks * 32 + (lane >> 4) * 16;
#pragma unroll
            for (int mt = 0; mt < 2; mt++) {
                ldsm4(ah[mt], sb + SAH + aoff + mt * 16 * GSTR);
                ldsm4(al[mt], sb + SAL + aoff + mt * 16 * GSTR);
            }
#pragma unroll
            for (int bp = 0; bp < 2; bp++) {
                ldsm4(bh[bp], sb + SBH + boff + bp * 16 * GSTR);
                ldsm4(bl[bp], sb + SBL + boff + bp * 16 * GSTR);
            }
#pragma unroll
            for (int mt = 0; mt < 2; mt++)
#pragma unroll
                for (int nt = 0; nt < 4; nt++) {
                    uint32_t h0 = bh[nt >> 1][nt & 1], h1 = bh[nt >> 1][(nt & 1) + 2];
                    uint32_t l0 = bl[nt >> 1][nt & 1], l1 = bl[nt >> 1][(nt & 1) + 2];
                    mma16816(d[mt][nt], ah[mt], h0, h1);
                    mma16816(d[mt][nt], al[mt], h0, h1);
                    mma16816(d[mt][nt], ah[mt], l0, l1);
                }
        }
    }

    // epilogue
#pragma unroll
    for (int mt = 0; mt < 2; mt++) {
        int r1 = row0 + wm * 32 + mt * 16 + (lane >> 2);
#pragma unroll
        for (int nt = 0; nt < 4; nt++) {
            int cc = col0 + wn * 32 + nt * 8 + (lane & 3) * 2;
            float b0 = bias[cc], b1 = bias[cc + 1];
            float v00 = d[mt][nt][0] + b0, v01 = d[mt][nt][1] + b1;
            float v10 = d[mt][nt][2] + b0, v11 = d[mt][nt][3] + b1;
            if (MODE == 0) {
                *(float2*)(out + (size_t)r1 * 512 + cc) = make_float2(v00, v01);
                *(float2*)(out + (size_t)(r1 + 8) * 512 + cc) = make_float2(v10, v11);
            } else {
                int hd = cc - col0;
#pragma unroll
                for (int rr = 0; rr < 2; rr++) {
                    int r = r1 + rr * 8;
                    float va0 = rr ? v10 : v00, va1 = rr ? v11 : v01;
                    int b = r >> 11, l = r & 2047;
                    size_t idx = (((size_t)(b * Hc + blockIdx.x)) * Lc + l) * HDc + hd;
                    __nv_bfloat16 ha = __float2bfloat16(va0), hb = __float2bfloat16(va1);
                    *(__nv_bfloat162*)(outh + idx) = __halves2bfloat162(ha, hb);
                    *(__nv_bfloat162*)(outl + idx) = __halves2bfloat162(
                        __float2bfloat16(va0 - __bfloat162float(ha)),
                        __float2bfloat16(va1 - __bfloat162float(hb)));
                }
            }
        }
    }
}

// ---------------------------------------------------------------------------
// Warp-MMA causal flash attention, cp.async double-buffered K/V.
// Grid (16, H, B), block 256 (8 warps), 2 CTAs/SM (regs capped 128).
// S-phase loads each K fragment once (kh: 2 mma-pairs, kl: 1).
// ---------------------------------------------------------------------------
__global__ void __launch_bounds__(256, 2) flash_mma() {
    extern __shared__ char smem[];
    const uint32_t sb = smem_u32(smem);
    const int t = threadIdx.x, lane = t & 31, w = t >> 5;
    const int qt = 15 - blockIdx.x;  // heavy tiles first
    const int h = blockIdx.y, b = blockIdx.z;
    const size_t base = ((size_t)(b * Hc + h)) * Lc * HDc;
    const uint32_t SQH = 0, SQL = 18432, SST = 36864, STSZ = 36864;
    const uint32_t OKL = 9216, OVH = 18432, OVL = 27648;

    const int njt = 2 * qt + 2;

    auto pf = [&](int jt, int st) {
        uint32_t dstb = sb + SST + st * STSZ;
#pragma unroll
        for (int i = 0; i < 2; i++) {
            int idx = i * 256 + t, r = idx >> 3, cb = (idx & 7) * 16, ce = (idx & 7) * 8;
            size_t g = base + (size_t)(jt * 64 + r) * HDc + ce;
            uint32_t d0 = dstb + r * GSTR + cb;
            cpasync16(d0,        g_Kh + g);
            cpasync16(d0 + OKL,  g_Kl + g);
            cpasync16(d0 + OVH,  g_Vh + g);
            cpasync16(d0 + OVL,  g_Vl + g);
        }
    };

    pf(0, 0);
    cp_commit();

    // load Q tile (128 rows x 64 bf16, hi+lo)
#pragma unroll
    for (int i = 0; i < 4; i++) {
        int idx = i * 256 + t, r = idx >> 3, cb = (idx & 7) * 16, ce = (idx & 7) * 8;
        size_t g = base + (size_t)(qt * 128 + r) * HDc + ce;
        *(uint4*)(smem + SQH + r * GSTR + cb) = *(const uint4*)(g_Qh + g);
        *(uint4*)(smem + SQL + r * GSTR + cb) = *(const uint4*)(g_Ql + g);
    }
    __syncthreads();

    uint32_t qfh[4][4], qfl[4][4];
#pragma unroll
    for (int ks = 0; ks < 4; ks++) {
        uint32_t a = (w * 16 + (lane & 15)) * GSTR + ks * 32 + (lane >> 4) * 16;
        ldsm4(qfh[ks], sb + SQH + a);
        ldsm4(qfl[ks], sb + SQL + a);
    }

    float o[8][4];
#pragma unroll
    for (int i = 0; i < 8; i++)
#pragma unroll
        for (int e = 0; e < 4; e++) o[i][e] = 0.f;
    float m0 = -1e30f, m1 = -1e30f, l0 = 0.f, l1 = 0.f;
    const float scale = 0.125f;
    const int qlo = qt * 128 + w * 16;

    for (int jt = 0; jt < njt; jt++) {
        if (jt + 1 < njt) pf(jt + 1, (jt + 1) & 1);
        cp_commit();
        cp_wait1();
        __syncthreads();

        const int J0 = jt * 64;
        const uint32_t stb = sb + SST + (jt & 1) * STSZ;

        if (J0 <= qlo + 15) {
            // ---- S = Q K^T, fragment-resident 3-pass ----
            float s[8][4];
#pragma unroll
            for (int i = 0; i < 8; i++)
#pragma unroll
                for (int e = 0; e < 4; e++) s[i][e] = 0.f;
#pragma unroll
            for (int ks = 0; ks < 4; ks++) {
#pragma unroll
                for (int bp = 0; bp < 4; bp++) {
                    uint32_t off = (bp * 16 + (lane & 15)) * GSTR + ks * 32 + (lane >> 4) * 16;
                    uint32_t kh[4], kl[4];
                    ldsm4(kh, stb + off);
                    mma16816(s[bp * 2],     qfh[ks], kh[0], kh[2]);
                    mma16816(s[bp * 2 + 1], qfh[ks], kh[1], kh[3]);
                    mma16816(s[bp * 2],     qfl[ks], kh[0], kh[2]);
                    mma16816(s[bp * 2 + 1], qfl[ks], kh[1], kh[3]);
                    ldsm4(kl, stb + OKL + off);
                    mma16816(s[bp * 2],     qfh[ks], kl[0], kl[2]);
                    mma16816(s[bp * 2 + 1], qfh[ks], kl[1], kl[3]);
                }
            }

            // ---- scale + causal mask ----
            if (J0 + 63 > qlo) {
                int q0 = qlo + (lane >> 2);
#pragma unroll
                for (int nt = 0; nt < 8; nt++) {
                    int kc = J0 + nt * 8 + (lane & 3) * 2;
                    s[nt][0] = (kc     <= q0)     ? s[nt][0] * scale : -1e30f;
                    s[nt][1] = (kc + 1 <= q0)     ? s[nt][1] * scale : -1e30f;
                    s[nt][2] = (kc     <= q0 + 8) ? s[nt][2] * scale : -1e30f;
                    s[nt][3] = (kc + 1 <= q0 + 8) ? s[nt][3] * scale : -1e30f;
                }
            } else {
#pragma unroll
                for (int nt = 0; nt < 8; nt++)
#pragma unroll
                    for (int e = 0; e < 4; e++) s[nt][e] *= scale;
            }

            // ---- online softmax ----
            float a0 = -1e30f, a1 = -1e30f;
#pragma unroll
            for (int nt = 0; nt < 8; nt++) {
                a0 = fmaxf(a0, fmaxf(s[nt][0], s[nt][1]));
                a1 = fmaxf(a1, fmaxf(s[nt][2], s[nt][3]));
            }
            a0 = fmaxf(a0, __shfl_xor_sync(0xffffffffu, a0, 1));
            a0 = fmaxf(a0, __shfl_xor_sync(0xffffffffu, a0, 2));
            a1 = fmaxf(a1, __shfl_xor_sync(0xffffffffu, a1, 1));
            a1 = fmaxf(a1, __shfl_xor_sync(0xffffffffu, a1, 2));
            float n0 = fmaxf(m0, a0), n1 = fmaxf(m1, a1);
            float c0 = __expf(m0 - n0), c1 = __expf(m1 - n1);
            m0 = n0; m1 = n1; l0 *= c0; l1 *= c1;
#pragma unroll
            for (int nt = 0; nt < 8; nt++) {
                o[nt][0] *= c0; o[nt][1] *= c0; o[nt][2] *= c1; o[nt][3] *= c1;
            }

            // ---- P = exp(S - m); PV accumulation ----
#pragma unroll
            for (int ks = 0; ks < 4; ks++) {
                float p[8];
                p[0] = __expf(s[2 * ks][0] - n0);     p[1] = __expf(s[2 * ks][1] - n0);
                p[2] = __expf(s[2 * ks][2] - n1);     p[3] = __expf(s[2 * ks][3] - n1);
                p[4] = __expf(s[2 * ks + 1][0] - n0); p[5] = __expf(s[2 * ks + 1][1] - n0);
                p[6] = __expf(s[2 * ks + 1][2] - n1); p[7] = __expf(s[2 * ks + 1][3] - n1);
                l0 += p[0] + p[1] + p[4] + p[5];
                l1 += p[2] + p[3] + p[6] + p[7];
                uint32_t ph[4], pl[4];
#pragma unroll
                for (int j = 0; j < 4; j++) {
                    float e0 = p[j * 2], e1 = p[j * 2 + 1];
                    ph[j] = packbf2(e0, e1);
                    __nv_bfloat162 hv = *(__nv_bfloat162*)&ph[j];
                    pl[j] = packbf2(e0 - __bfloat162float(hv.x), e1 - __bfloat162float(hv.y));
                }
#pragma unroll
                for (int np = 0; np < 4; np++) {
                    uint32_t a = stb + OVH + (ks * 16 + (lane & 15)) * GSTR + np * 32 + (lane >> 4) * 16;
                    uint32_t vh[4], vl[4];
                    ldsm4t(vh, a);
                    mma16816(o[np * 2],     ph, vh[0], vh[1]);
                    mma16816(o[np * 2 + 1], ph, vh[2], vh[3]);
                    mma16816(o[np * 2],     pl, vh[0], vh[1]);
                    mma16816(o[np * 2 + 1], pl, vh[2], vh[3]);
                    ldsm4t(vl, a + (OVL - OVH));
                    mma16816(o[np * 2],     ph, vl[0], vl[1]);
                    mma16816(o[np * 2 + 1], ph, vl[2], vl[3]);
                }
            }
        }
        __syncthreads();
    }

    // ---- finalize: write bf16 hi/lo ctx in [B,L,D] ----
    l0 += __shfl_xor_sync(0xffffffffu, l0, 1);
    l0 += __shfl_xor_sync(0xffffffffu, l0, 2);
    l1 += __shfl_xor_sync(0xffffffffu, l1, 1);
    l1 += __shfl_xor_sync(0xffffffffu, l1, 2);
    float i0 = 1.f / l0, i1 = 1.f / l1;
    int qrow = qt * 128 + w * 16 + (lane >> 2);
    size_t r0 = (size_t)b * Lc + qrow;
#pragma unroll
    for (int nt = 0; nt < 8; nt++) {
        int cc = h * HDc + nt * 8 + (lane & 3) * 2;
#pragma unroll
        for (int rr = 0; rr < 2; rr++) {
            float va0 = (rr ? o[nt][2] * i1 : o[nt][0] * i0);
            float va1 = (rr ? o[nt][3] * i1 : o[nt][1] * i0);
            size_t idx = (r0 + rr * 8) * Dc + cc;
            __nv_bfloat16 ha = __float2bfloat16(va0), hb = __float2bfloat16(va1);
            *(__nv_bfloat162*)(g_CXh + idx) = __halves2bfloat162(ha, hb);
            *(__nv_bfloat162*)(g_CXl + idx) = __halves2bfloat162(
                __float2bfloat16(va0 - __bfloat162float(ha)),
                __float2bfloat16(va1 - __bfloat162float(hb)));
        }
    }
}

// ---------------------------------------------------------------------------
extern "C" void kernel_launch(void* const* d_in, const int* in_sizes, int n_in,
                              void* d_out, int out_size) {
    const float* q  = (const float*)d_in[0];
    const float* k  = (const float*)d_in[1];
    const float* v  = (const float*)d_in[2];
    const float* Wq = (const float*)d_in[4];
    const float* bq = (const float*)d_in[5];
    const float* Wk = (const float*)d_in[6];
    const float* bk = (const float*)d_in[7];
    const float* Wv = (const float*)d_in[8];
    const float* bv = (const float*)d_in[9];
    const float* Wo = (const float*)d_in[10];
    const float* bo = (const float*)d_in[11];
    float* out = (float*)d_out;

    __nv_bfloat16 *Qh, *Ql, *Kh, *Kl, *Vh, *Vl, *CXh, *CXl;
    cudaGetSymbolAddress((void**)&Qh, g_Qh);
    cudaGetSymbolAddress((void**)&Ql, g_Ql);
    cudaGetSymbolAddress((void**)&Kh, g_Kh);
    cudaGetSymbolAddress((void**)&Kl, g_Kl);
    cudaGetSymbolAddress((void**)&Vh, g_Vh);
    cudaGetSymbolAddress((void**)&Vl, g_Vl);
    cudaGetSymbolAddress((void**)&CXh, g_CXh);
    cudaGetSymbolAddress((void**)&CXl, g_CXl);

    const int gsmem = 55296;
    const int fsmem = 36864 + 2 * 36864;  // 110592
    cudaFuncSetAttribute(gemm_mma<0>, cudaFuncAttributeMaxDynamicSharedMemorySize, gsmem);
    cudaFuncSetAttribute(gemm_mma<1>, cudaFuncAttributeMaxDynamicSharedMemorySize, gsmem);
    cudaFuncSetAttribute(flash_mma, cudaFuncAttributeMaxDynamicSharedMemorySize, fsmem);

    dim3 grd_gemm(Dc / 64, BL / 128);  // 8 x 64

    gemm_mma<1><<<grd_gemm, 256, gsmem>>>(q, nullptr, nullptr, Wq, bq, nullptr, Qh, Ql);
    gemm_mma<1><<<grd_gemm, 256, gsmem>>>(k, nullptr, nullptr, Wk, bk, nullptr, Kh, Kl);
    gemm_mma<1><<<grd_gemm, 256, gsmem>>>(v, nullptr, nullptr, Wv, bv, nullptr, Vh, Vl);

    dim3 grd_fa(Lc / 128, Hc, Bc);     // 16 x 8 x 4
    flash_mma<<<grd_fa, 256, fsmem>>>();

    gemm_mma<0><<<grd_gemm, 256, gsmem>>>(nullptr, CXh, CXl, Wo, bo, out, nullptr, nullptr);
}

// round 10
// speedup vs baseline: 1.3769x; 1.1303x over previous
#include <cuda_runtime.h>
#include <cuda_fp16.h>
#include <math.h>
#include <stdint.h>

#define Bc 4
#define Lc 2048
#define Dc 512
#define Hc 8
#define HDc 64
#define BL (Bc*Lc)

// ---------------- scratch (device globals; no allocation allowed) ----------
__device__ __half g_Qh[Bc*Hc*Lc*HDc];
__device__ __half g_Ql[Bc*Hc*Lc*HDc];
__device__ __half g_Kh[Bc*Hc*Lc*HDc];
__device__ __half g_Kl[Bc*Hc*Lc*HDc];
__device__ __half g_V [Bc*Hc*Lc*HDc];
__device__ __half g_CXh[BL*Dc];
__device__ __half g_CXl[BL*Dc];

// ---------------- helpers ---------------------------------------------------
__device__ __forceinline__ uint32_t smem_u32(const void* p) {
    uint32_t a;
    asm("{ .reg .u64 t; cvta.to.shared.u64 t, %1; cvt.u32.u64 %0, t; }"
        : "=r"(a) : "l"(p));
    return a;
}
__device__ __forceinline__ void ldsm4(uint32_t* r, uint32_t addr) {
    asm volatile("ldmatrix.sync.aligned.m8n8.x4.shared.b16 {%0,%1,%2,%3}, [%4];"
                 : "=r"(r[0]), "=r"(r[1]), "=r"(r[2]), "=r"(r[3]) : "r"(addr));
}
__device__ __forceinline__ void ldsm4t(uint32_t* r, uint32_t addr) {
    asm volatile("ldmatrix.sync.aligned.m8n8.x4.trans.shared.b16 {%0,%1,%2,%3}, [%4];"
                 : "=r"(r[0]), "=r"(r[1]), "=r"(r[2]), "=r"(r[3]) : "r"(addr));
}
__device__ __forceinline__ void mma16816(float* d, const uint32_t* a,
                                         uint32_t b0, uint32_t b1) {
    asm volatile("mma.sync.aligned.m16n8k16.row.col.f32.f16.f16.f32 "
                 "{%0,%1,%2,%3}, {%4,%5,%6,%7}, {%8,%9}, {%0,%1,%2,%3};"
                 : "+f"(d[0]), "+f"(d[1]), "+f"(d[2]), "+f"(d[3])
                 : "r"(a[0]), "r"(a[1]), "r"(a[2]), "r"(a[3]), "r"(b0), "r"(b1));
}
__device__ __forceinline__ uint32_t packh2(float a, float b) {
    __half2 v = __floats2half2_rn(a, b);
    return *(uint32_t*)&v;
}
__device__ __forceinline__ void cpasync16(uint32_t s, const void* g) {
    asm volatile("cp.async.cg.shared.global [%0], [%1], 16;" :: "r"(s), "l"(g) : "memory");
}
__device__ __forceinline__ void cp_commit() {
    asm volatile("cp.async.commit_group;" ::: "memory");
}
__device__ __forceinline__ void cp_wait1() {
    asm volatile("cp.async.wait_group 1;" ::: "memory");
}
// 8 fp32 -> fp16 hi uint4 + fp16 lo uint4
__device__ __forceinline__ void split8h(const float4 v0, const float4 v1,
                                        uint4& hi, uint4& lo) {
    hi.x = packh2(v0.x, v0.y); hi.y = packh2(v0.z, v0.w);
    hi.z = packh2(v1.x, v1.y); hi.w = packh2(v1.z, v1.w);
    __half2 h;
    h = *(__half2*)&hi.x;
    lo.x = packh2(v0.x - __half2float(h.x), v0.y - __half2float(h.y));
    h = *(__half2*)&hi.y;
    lo.y = packh2(v0.z - __half2float(h.x), v0.w - __half2float(h.y));
    h = *(__half2*)&hi.z;
    lo.z = packh2(v1.x - __half2float(h.x), v1.y - __half2float(h.y));
    h = *(__half2*)&hi.w;
    lo.w = packh2(v1.z - __half2float(h.x), v1.w - __half2float(h.y));
}
// 8 fp32 -> single fp16 uint4
__device__ __forceinline__ uint4 cvt8h(const float4 v0, const float4 v1) {
    uint4 r;
    r.x = packh2(v0.x, v0.y); r.y = packh2(v0.z, v0.w);
    r.z = packh2(v1.x, v1.y); r.w = packh2(v1.z, v1.w);
    return r;
}

// ---------------------------------------------------------------------------
// Warp-MMA GEMM: out = A @ W^T + bias.
// MODE 1 (Q/K proj): A fp32, W fp32->fp16 hi/lo (3-pass), out fp16 hi/lo [B,H,L,HD]
// MODE 2 (V proj):   A fp32, W fp32->fp16 single (2-pass), out fp16 single [B,H,L,HD]
// MODE 0 (out proj): A fp16 hi/lo, W single (2-pass), out fp32 [M,512]
// Block 256 thr (8 warps), tile 128x64, warp 32x32, BK=64.
// ---------------------------------------------------------------------------
#define GSTR 144  // smem row stride bytes (64 fp16 = 128B + 16 pad)
template<int MODE>
__global__ void __launch_bounds__(256) gemm_mma(
    const float* __restrict__ Afp,
    const __half* __restrict__ Ah, const __half* __restrict__ Al,
    const float* __restrict__ W,
    const float* __restrict__ bias, float* __restrict__ out,
    __half* __restrict__ outh, __half* __restrict__ outl) {
    extern __shared__ char smem[];
    const uint32_t sb = smem_u32(smem);
    const int t = threadIdx.x, lane = t & 31, wid = t >> 5;
    const int wm = wid & 3, wn = wid >> 2;
    const int row0 = blockIdx.y * 128, col0 = blockIdx.x * 64;
    const uint32_t SAH = 0, SAL = 18432, SBH = 36864, SBL = 46080;
    constexpr bool WSPLIT = (MODE == 1);

    float d[2][4][4];
#pragma unroll
    for (int i = 0; i < 2; i++)
#pragma unroll
        for (int j = 0; j < 4; j++)
#pragma unroll
            for (int e = 0; e < 4; e++) d[i][j][e] = 0.f;

    float4 va[4][2];
    uint4 ra_h[4], ra_l[4];
    float4 vb[2][2];

    auto gload = [&](int kc) {
        const int k0 = kc * 64;
#pragma unroll
        for (int i = 0; i < 4; i++) {
            int idx = i * 256 + t, r = idx >> 3, ce = (idx & 7) * 8;
            if (MODE >= 1) {
                const float4* src = (const float4*)(Afp + (size_t)(row0 + r) * 512 + k0 + ce);
                va[i][0] = src[0]; va[i][1] = src[1];
            } else {
                size_t g = (size_t)(row0 + r) * 512 + k0 + ce;
                ra_h[i] = *(const uint4*)(Ah + g);
                ra_l[i] = *(const uint4*)(Al + g);
            }
        }
#pragma unroll
        for (int i = 0; i < 2; i++) {
            int idx = i * 256 + t, r = idx >> 3, ce = (idx & 7) * 8;
            const float4* src = (const float4*)(W + (size_t)(col0 + r) * 512 + k0 + ce);
            vb[i][0] = src[0]; vb[i][1] = src[1];
        }
    };
    auto sstore = [&]() {
#pragma unroll
        for (int i = 0; i < 4; i++) {
            int idx = i * 256 + t, r = idx >> 3, cb = (idx & 7) * 16;
            uint4 hi, lo;
            if (MODE >= 1) split8h(va[i][0], va[i][1], hi, lo);
            else { hi = ra_h[i]; lo = ra_l[i]; }
            *(uint4*)(smem + SAH + r * GSTR + cb) = hi;
            *(uint4*)(smem + SAL + r * GSTR + cb) = lo;
        }
#pragma unroll
        for (int i = 0; i < 2; i++) {
            int idx = i * 256 + t, r = idx >> 3, cb = (idx & 7) * 16;
            if (WSPLIT) {
                uint4 hi, lo;
                split8h(vb[i][0], vb[i][1], hi, lo);
                *(uint4*)(smem + SBH + r * GSTR + cb) = hi;
                *(uint4*)(smem + SBL + r * GSTR + cb) = lo;
            } else {
                *(uint4*)(smem + SBH + r * GSTR + cb) = cvt8h(vb[i][0], vb[i][1]);
            }
        }
    };

    gload(0);
    for (int c = 0; c < 8; c++) {
        __syncthreads();
        sstore();
        __syncthreads();
        if (c < 7) gload(c + 1);
#pragma unroll
        for (int ks = 0; ks < 4; ks++) {
            uint32_t ah[2][4], al[2][4], bh[2][4], bl[2][4];
            uint32_t aoff = (wm * 32 + (lane & 15)) * GSTR + ks * 32 + (lane >> 4) * 16;
            uint32_t boff = (wn * 32 + (lane & 15)) * GSTR + ks * 32 + (lane >> 4) * 16;
#pragma unroll
            for (int mt = 0; mt < 2; mt++) {
                ldsm4(ah[mt], sb + SAH + aoff + mt * 16 * GSTR);
                ldsm4(al[mt], sb + SAL + aoff + mt * 16 * GSTR);
            }
#pragma unroll
            for (int bp = 0; bp < 2; bp++) {
                ldsm4(bh[bp], sb + SBH + boff + bp * 16 * GSTR);
                if (WSPLIT) ldsm4(bl[bp], sb + SBL + boff + bp * 16 * GSTR);
            }
#pragma unroll
            for (int mt = 0; mt < 2; mt++)
#pragma unroll
                for (int nt = 0; nt < 4; nt++) {
                    uint32_t h0 = bh[nt >> 1][nt & 1], h1 = bh[nt >> 1][(nt & 1) + 2];
                    mma16816(d[mt][nt], ah[mt], h0, h1);
                    mma16816(d[mt][nt], al[mt], h0, h1);
                    if (WSPLIT) {
                        uint32_t l0 = bl[nt >> 1][nt & 1], l1 = bl[nt >> 1][(nt & 1) + 2];
                        mma16816(d[mt][nt], ah[mt], l0, l1);
                    }
                }
        }
    }

    // epilogue
#pragma unroll
    for (int mt = 0; mt < 2; mt++) {
        int r1 = row0 + wm * 32 + mt * 16 + (lane >> 2);
#pragma unroll
        for (int nt = 0; nt < 4; nt++) {
            int cc = col0 + wn * 32 + nt * 8 + (lane & 3) * 2;
            float b0 = bias[cc], b1 = bias[cc + 1];
            float v00 = d[mt][nt][0] + b0, v01 = d[mt][nt][1] + b1;
            float v10 = d[mt][nt][2] + b0, v11 = d[mt][nt][3] + b1;
            if (MODE == 0) {
                *(float2*)(out + (size_t)r1 * 512 + cc) = make_float2(v00, v01);
                *(float2*)(out + (size_t)(r1 + 8) * 512 + cc) = make_float2(v10, v11);
            } else {
                int hd = cc - col0;
#pragma unroll
                for (int rr = 0; rr < 2; rr++) {
                    int r = r1 + rr * 8;
                    float va0 = rr ? v10 : v00, va1 = rr ? v11 : v01;
                    int b = r >> 11, l = r & 2047;
                    size_t idx = (((size_t)(b * Hc + blockIdx.x)) * Lc + l) * HDc + hd;
                    if (MODE == 2) {
                        *(uint32_t*)(outh + idx) = packh2(va0, va1);
                    } else {
                        uint32_t hi = packh2(va0, va1);
                        __half2 hv = *(__half2*)&hi;
                        *(uint32_t*)(outh + idx) = hi;
                        *(uint32_t*)(outl + idx) =
                            packh2(va0 - __half2float(hv.x), va1 - __half2float(hv.y));
                    }
                }
            }
        }
    }
}

// ---------------------------------------------------------------------------
// Warp-MMA causal flash attention, fp16, 3-stage cp.async pipeline (stage 2
// overlays the dead Q-staging region), ONE barrier per tile.
// Grid (16, H, B), block 256 (8 warps), 2 CTAs/SM. K hi/lo (3-pass S),
// V single (2-pass PV, P split exact). Output fp16 hi/lo ctx [B,L,D].
// ---------------------------------------------------------------------------
__global__ void __launch_bounds__(256, 2) flash_mma() {
    extern __shared__ char smem[];
    const uint32_t sb = smem_u32(smem);
    const int t = threadIdx.x, lane = t & 31, w = t >> 5;
    const int qt = 15 - blockIdx.x;  // heavy tiles first
    const int h = blockIdx.y, b = blockIdx.z;
    const size_t base = ((size_t)(b * Hc + h)) * Lc * HDc;
    const uint32_t SQH = 0, SQL = 18432;
    const uint32_t OKL = 9216, OV = 18432, STSZ = 27648, SST = 36864;

    const int njt = 2 * qt + 2;

    auto stage_base = [&](int jt) -> uint32_t {
        int s = jt % 3;
        return (s == 2) ? sb : sb + SST + (uint32_t)s * STSZ;
    };
    auto pf = [&](int jt) {
        uint32_t dstb = stage_base(jt);
#pragma unroll
        for (int i = 0; i < 2; i++) {
            int idx = i * 256 + t, r = idx >> 3, cb = (idx & 7) * 16, ce = (idx & 7) * 8;
            size_t g = base + (size_t)(jt * 64 + r) * HDc + ce;
            uint32_t d0 = dstb + r * GSTR + cb;
            cpasync16(d0,       g_Kh + g);
            cpasync16(d0 + OKL, g_Kl + g);
            cpasync16(d0 + OV,  g_V + g);
        }
    };

    // stages 0,1 in flight (groups 0,1)
    pf(0); cp_commit();
    pf(1); cp_commit();

    // load Q tile (128 rows x 64 fp16, hi+lo)
#pragma unroll
    for (int i = 0; i < 4; i++) {
        int idx = i * 256 + t, r = idx >> 3, cb = (idx & 7) * 16, ce = (idx & 7) * 8;
        size_t g = base + (size_t)(qt * 128 + r) * HDc + ce;
        *(uint4*)(smem + SQH + r * GSTR + cb) = *(const uint4*)(g_Qh + g);
        *(uint4*)(smem + SQL + r * GSTR + cb) = *(const uint4*)(g_Ql + g);
    }
    __syncthreads();

    uint32_t qfh[4][4], qfl[4][4];
#pragma unroll
    for (int ks = 0; ks < 4; ks++) {
        uint32_t a = (w * 16 + (lane & 15)) * GSTR + ks * 32 + (lane >> 4) * 16;
        ldsm4(qfh[ks], sb + SQH + a);
        ldsm4(qfl[ks], sb + SQL + a);
    }

    float o[8][4];
#pragma unroll
    for (int i = 0; i < 8; i++)
#pragma unroll
        for (int e = 0; e < 4; e++) o[i][e] = 0.f;
    float m0 = -1e30f, m1 = -1e30f, l0 = 0.f, l1 = 0.f;
    const float scale = 0.125f;
    const int qlo = qt * 128 + w * 16;

    for (int jt = 0; jt < njt; jt++) {
        cp_wait1();            // stage jt's group done (for this thread)
        __syncthreads();       // all threads' stage-jt data resident; stage (jt+2)%3 free
        if (jt + 2 < njt) pf(jt + 2);
        cp_commit();           // unconditional: keep group counting aligned

        const int J0 = jt * 64;
        const uint32_t stb = stage_base(jt);

        if (J0 <= qlo + 15) {
            // ---- S = Q K^T (K hi/lo, 3 logical passes) ----
            float s[8][4];
#pragma unroll
            for (int i = 0; i < 8; i++)
#pragma unroll
                for (int e = 0; e < 4; e++) s[i][e] = 0.f;
#pragma unroll
            for (int ks = 0; ks < 4; ks++) {
#pragma unroll
                for (int bp = 0; bp < 4; bp++) {
                    if (J0 + bp * 16 > qlo + 15) continue;  // fully masked cols
                    uint32_t off = (bp * 16 + (lane & 15)) * GSTR + ks * 32 + (lane >> 4) * 16;
                    uint32_t kh[4], kl[4];
                    ldsm4(kh, stb + off);
                    mma16816(s[bp * 2],     qfh[ks], kh[0], kh[2]);
                    mma16816(s[bp * 2 + 1], qfh[ks], kh[1], kh[3]);
                    mma16816(s[bp * 2],     qfl[ks], kh[0], kh[2]);
                    mma16816(s[bp * 2 + 1], qfl[ks], kh[1], kh[3]);
                    ldsm4(kl, stb + OKL + off);
                    mma16816(s[bp * 2],     qfh[ks], kl[0], kl[2]);
                    mma16816(s[bp * 2 + 1], qfh[ks], kl[1], kl[3]);
                }
            }

            // ---- scale + causal mask ----
            if (J0 + 63 > qlo) {
                int q0 = qlo + (lane >> 2);
#pragma unroll
                for (int nt = 0; nt < 8; nt++) {
                    int kc = J0 + nt * 8 + (lane & 3) * 2;
                    s[nt][0] = (kc     <= q0)     ? s[nt][0] * scale : -1e30f;
                    s[nt][1] = (kc + 1 <= q0)     ? s[nt][1] * scale : -1e30f;
                    s[nt][2] = (kc     <= q0 + 8) ? s[nt][2] * scale : -1e30f;
                    s[nt][3] = (kc + 1 <= q0 + 8) ? s[nt][3] * scale : -1e30f;
                }
            } else {
#pragma unroll
                for (int nt = 0; nt < 8; nt++)
#pragma unroll
                    for (int e = 0; e < 4; e++) s[nt][e] *= scale;
            }

            // ---- online softmax ----
            float a0 = -1e30f, a1 = -1e30f;
#pragma unroll
            for (int nt = 0; nt < 8; nt++) {
                a0 = fmaxf(a0, fmaxf(s[nt][0], s[nt][1]));
                a1 = fmaxf(a1, fmaxf(s[nt][2], s[nt][3]));
            }
            a0 = fmaxf(a0, __shfl_xor_sync(0xffffffffu, a0, 1));
            a0 = fmaxf(a0, __shfl_xor_sync(0xffffffffu, a0, 2));
            a1 = fmaxf(a1, __shfl_xor_sync(0xffffffffu, a1, 1));
            a1 = fmaxf(a1, __shfl_xor_sync(0xffffffffu, a1, 2));
            float n0 = fmaxf(m0, a0), n1 = fmaxf(m1, a1);
            float c0 = __expf(m0 - n0), c1 = __expf(m1 - n1);
            m0 = n0; m1 = n1; l0 *= c0; l1 *= c1;
#pragma unroll
            for (int nt = 0; nt < 8; nt++) {
                o[nt][0] *= c0; o[nt][1] *= c0; o[nt][2] *= c1; o[nt][3] *= c1;
            }

            // ---- P = exp(S - m) split exactly; O += P V (V single, 2 passes) ----
#pragma unroll
            for (int ks = 0; ks < 4; ks++) {
                if (J0 + ks * 16 > qlo + 15) continue;  // p==0 there
                float p[8];
                p[0] = __expf(s[2 * ks][0] - n0);     p[1] = __expf(s[2 * ks][1] - n0);
                p[2] = __expf(s[2 * ks][2] - n1);     p[3] = __expf(s[2 * ks][3] - n1);
                p[4] = __expf(s[2 * ks + 1][0] - n0); p[5] = __expf(s[2 * ks + 1][1] - n0);
                p[6] = __expf(s[2 * ks + 1][2] - n1); p[7] = __expf(s[2 * ks + 1][3] - n1);
                l0 += p[0] + p[1] + p[4] + p[5];
                l1 += p[2] + p[3] + p[6] + p[7];
                uint32_t ph[4], pl[4];
#pragma unroll
                for (int j = 0; j < 4; j++) {
                    float e0 = p[j * 2], e1 = p[j * 2 + 1];
                    ph[j] = packh2(e0, e1);
                    __half2 hv = *(__half2*)&ph[j];
                    pl[j] = packh2(e0 - __half2float(hv.x), e1 - __half2float(hv.y));
                }
#pragma unroll
                for (int np = 0; np < 4; np++) {
                    uint32_t a = stb + OV + (ks * 16 + (lane & 15)) * GSTR + np * 32 + (lane >> 4) * 16;
                    uint32_t vh[4];
                    ldsm4t(vh, a);
                    mma16816(o[np * 2],     ph, vh[0], vh[1]);
                    mma16816(o[np * 2 + 1], ph, vh[2], vh[3]);
                    mma16816(o[np * 2],     pl, vh[0], vh[1]);
                    mma16816(o[np * 2 + 1], pl, vh[2], vh[3]);
                }
            }
        }
    }

    // ---- finalize: write fp16 hi/lo ctx in [B,L,D] ----
    l0 += __shfl_xor_sync(0xffffffffu, l0, 1);
    l0 += __shfl_xor_sync(0xffffffffu, l0, 2);
    l1 += __shfl_xor_sync(0xffffffffu, l1, 1);
    l1 += __shfl_xor_sync(0xffffffffu, l1, 2);
    float i0 = 1.f / l0, i1 = 1.f / l1;
    int qrow = qt * 128 + w * 16 + (lane >> 2);
    size_t r0 = (size_t)b * Lc + qrow;
#pragma unroll
    for (int nt = 0; nt < 8; nt++) {
        int cc = h * HDc + nt * 8 + (lane & 3) * 2;
#pragma unroll
        for (int rr = 0; rr < 2; rr++) {
            float va0 = (rr ? o[nt][2] * i1 : o[nt][0] * i0);
            float va1 = (rr ? o[nt][3] * i1 : o[nt][1] * i0);
            size_t idx = (r0 + rr * 8) * Dc + cc;
            uint32_t hi = packh2(va0, va1);
            __half2 hv = *(__half2*)&hi;
            *(uint32_t*)(g_CXh + idx) = hi;
            *(uint32_t*)(g_CXl + idx) =
                packh2(va0 - __half2float(hv.x), va1 - __half2float(hv.y));
        }
    }
}

// ---------------------------------------------------------------------------
extern "C" void kernel_launch(void* const* d_in, const int* in_sizes, int n_in,
                              void* d_out, int out_size) {
    const float* q  = (const float*)d_in[0];
    const float* k  = (const float*)d_in[1];
    const float* v  = (const float*)d_in[2];
    const float* Wq = (const float*)d_in[4];
    const float* bq = (const float*)d_in[5];
    const float* Wk = (const float*)d_in[6];
    const float* bk = (const float*)d_in[7];
    const float* Wv = (const float*)d_in[8];
    const float* bv = (const float*)d_in[9];
    const float* Wo = (const float*)d_in[10];
    const float* bo = (const float*)d_in[11];
    float* out = (float*)d_out;

    __half *Qh, *Ql, *Kh, *Kl, *V, *CXh, *CXl;
    cudaGetSymbolAddress((void**)&Qh, g_Qh);
    cudaGetSymbolAddress((void**)&Ql, g_Ql);
    cudaGetSymbolAddress((void**)&Kh, g_Kh);
    cudaGetSymbolAddress((void**)&Kl, g_Kl);
    cudaGetSymbolAddress((void**)&V,  g_V);
    cudaGetSymbolAddress((void**)&CXh, g_CXh);
    cudaGetSymbolAddress((void**)&CXl, g_CXl);

    const int gsmem = 55296;
    const int fsmem = 36864 + 2 * 27648;  // 92160 (stage 2 overlays Q region)
    cudaFuncSetAttribute(gemm_mma<0>, cudaFuncAttributeMaxDynamicSharedMemorySize, gsmem);
    cudaFuncSetAttribute(gemm_mma<1>, cudaFuncAttributeMaxDynamicSharedMemorySize, gsmem);
    cudaFuncSetAttribute(gemm_mma<2>, cudaFuncAttributeMaxDynamicSharedMemorySize, gsmem);
    cudaFuncSetAttribute(flash_mma, cudaFuncAttributeMaxDynamicSharedMemorySize, fsmem);

    dim3 grd_gemm(Dc / 64, BL / 128);  // 8 x 64

    gemm_mma<1><<<grd_gemm, 256, gsmem>>>(q, nullptr, nullptr, Wq, bq, nullptr, Qh, Ql);
    gemm_mma<1><<<grd_gemm, 256, gsmem>>>(k, nullptr, nullptr, Wk, bk, nullptr, Kh, Kl);
    gemm_mma<2><<<grd_gemm, 256, gsmem>>>(v, nullptr, nullptr, Wv, bv, nullptr, V, nullptr);

    dim3 grd_fa(Lc / 128, Hc, Bc);     // 16 x 8 x 4
    flash_mma<<<grd_fa, 256, fsmem>>>();

    gemm_mma<0><<<grd_gemm, 256, gsmem>>>(nullptr, CXh, CXl, Wo, bo, out, nullptr, nullptr);
}

// round 12
// speedup vs baseline: 1.4318x; 1.0399x over previous
#include <cuda_runtime.h>
#include <cuda_fp16.h>
#include <math.h>
#include <stdint.h>

#define Bc 4
#define Lc 2048
#define Dc 512
#define Hc 8
#define HDc 64
#define BL (Bc*Lc)

// ---------------- scratch (device globals; no allocation allowed) ----------
__device__ __half g_Qh[Bc*Hc*Lc*HDc];
__device__ __half g_Ql[Bc*Hc*Lc*HDc];
__device__ __half g_Kh[Bc*Hc*Lc*HDc];
__device__ __half g_Kl[Bc*Hc*Lc*HDc];
__device__ __half g_V [Bc*Hc*Lc*HDc];
__device__ __half g_CXh[BL*Dc];
__device__ __half g_CXl[BL*Dc];
__device__ __half g_Ah[BL*Dc];        // converted activation (reused q->k->v)
__device__ __half g_Al[BL*Dc];
__device__ __half g_Wh[4*Dc*Dc];      // converted weights (q,k,v,o)
__device__ __half g_Wl[4*Dc*Dc];

// ---------------- helpers ---------------------------------------------------
__device__ __forceinline__ uint32_t smem_u32(const void* p) {
    uint32_t a;
    asm("{ .reg .u64 t; cvta.to.shared.u64 t, %1; cvt.u32.u64 %0, t; }"
        : "=r"(a) : "l"(p));
    return a;
}
__device__ __forceinline__ void ldsm4(uint32_t* r, uint32_t addr) {
    asm volatile("ldmatrix.sync.aligned.m8n8.x4.shared.b16 {%0,%1,%2,%3}, [%4];"
                 : "=r"(r[0]), "=r"(r[1]), "=r"(r[2]), "=r"(r[3]) : "r"(addr));
}
__device__ __forceinline__ void ldsm4t(uint32_t* r, uint32_t addr) {
    asm volatile("ldmatrix.sync.aligned.m8n8.x4.trans.shared.b16 {%0,%1,%2,%3}, [%4];"
                 : "=r"(r[0]), "=r"(r[1]), "=r"(r[2]), "=r"(r[3]) : "r"(addr));
}
__device__ __forceinline__ void mma16816(float* d, const uint32_t* a,
                                         uint32_t b0, uint32_t b1) {
    asm volatile("mma.sync.aligned.m16n8k16.row.col.f32.f16.f16.f32 "
                 "{%0,%1,%2,%3}, {%4,%5,%6,%7}, {%8,%9}, {%0,%1,%2,%3};"
                 : "+f"(d[0]), "+f"(d[1]), "+f"(d[2]), "+f"(d[3])
                 : "r"(a[0]), "r"(a[1]), "r"(a[2]), "r"(a[3]), "r"(b0), "r"(b1));
}
__device__ __forceinline__ uint32_t packh2(float a, float b) {
    __half2 v = __floats2half2_rn(a, b);
    return *(uint32_t*)&v;
}
__device__ __forceinline__ float ex2(float x) {
    float r;
    asm("ex2.approx.f32 %0, %1;" : "=f"(r) : "f"(x));
    return r;
}
__device__ __forceinline__ void cpasync16(uint32_t s, const void* g) {
    asm volatile("cp.async.cg.shared.global [%0], [%1], 16;" :: "r"(s), "l"(g) : "memory");
}
__device__ __forceinline__ void cp_commit() {
    asm volatile("cp.async.commit_group;" ::: "memory");
}
__device__ __forceinline__ void cp_wait1() {
    asm volatile("cp.async.wait_group 1;" ::: "memory");
}

// ---------------------------------------------------------------------------
// fp32 -> fp16 hi/lo split conversion (4 elems/thread)
// ---------------------------------------------------------------------------
__global__ void cvt_hilo(const float4* __restrict__ x, uint2* __restrict__ hi,
                         uint2* __restrict__ lo, int n4) {
    int i = blockIdx.x * blockDim.x + threadIdx.x;
    if (i < n4) {
        float4 v = x[i];
        uint2 h, l;
        h.x = packh2(v.x, v.y); h.y = packh2(v.z, v.w);
        __half2 a = *(__half2*)&h.x, b = *(__half2*)&h.y;
        l.x = packh2(v.x - __half2float(a.x), v.y - __half2float(a.y));
        l.y = packh2(v.z - __half2float(b.x), v.w - __half2float(b.y));
        hi[i] = h; lo[i] = l;
    }
}

// ---------------------------------------------------------------------------
// Warp-MMA GEMM, pure fp16 operands, cp.async double-buffered, 2 CTAs/SM.
// out = A @ W^T + bias.
// MODE 1 (Q/K proj): 3-pass (AhBh+AlBh+AhBl), out fp16 hi/lo [B,H,L,HD]
// MODE 2 (V proj):   2-pass (AhBh+AlBh),      out fp16 single [B,H,L,HD]
// MODE 0 (out proj): 2-pass,                  out fp32 [M,512]
// Block 256 thr (8 warps), tile 128x64, warp 32x32, BK=64.
// ---------------------------------------------------------------------------
#define GSTR 144  // smem row stride bytes (64 fp16 = 128B + 16 pad)
template<int MODE>
__global__ void __launch_bounds__(256, 2) gemm_mma(
    const __half* __restrict__ Ah, const __half* __restrict__ Al,
    const __half* __restrict__ Bh, const __half* __restrict__ Bl,
    const float* __restrict__ bias, float* __restrict__ out,
    __half* __restrict__ outh, __half* __restrict__ outl) {
    extern __shared__ char smem[];
    const uint32_t sb = smem_u32(smem);
    const int t = threadIdx.x, lane = t & 31, wid = t >> 5;
    const int wm = wid & 3, wn = wid >> 2;
    const int row0 = blockIdx.y * 128, col0 = blockIdx.x * 64;
    constexpr bool WSPLIT = (MODE == 1);
    const uint32_t SAL = 18432, SBH = 36864, SBL = 46080, STG = 55296;

    float d[2][4][4];
#pragma unroll
    for (int i = 0; i < 2; i++)
#pragma unroll
        for (int j = 0; j < 4; j++)
#pragma unroll
            for (int e = 0; e < 4; e++) d[i][j][e] = 0.f;

    auto pf = [&](int kc, int st) {
        const int k0 = kc * 64;
        uint32_t dstb = sb + st * STG;
#pragma unroll
        for (int i = 0; i < 4; i++) {
            int idx = i * 256 + t, r = idx >> 3, c = idx & 7;
            size_t g = (size_t)(row0 + r) * 512 + k0 + c * 8;
            uint32_t d0 = dstb + r * GSTR + c * 16;
            cpasync16(d0,       Ah + g);
            cpasync16(d0 + SAL, Al + g);
        }
#pragma unroll
        for (int i = 0; i < 2; i++) {
            int idx = i * 256 + t, r = idx >> 3, c = idx & 7;
            size_t g = (size_t)(col0 + r) * 512 + k0 + c * 8;
            uint32_t d0 = dstb + r * GSTR + c * 16;
            cpasync16(d0 + SBH, Bh + g);
            if (WSPLIT) cpasync16(d0 + SBL, Bl + g);
        }
    };

    pf(0, 0); cp_commit();
    pf(1, 1); cp_commit();

    for (int c = 0; c < 8; c++) {
        cp_wait1();
        __syncthreads();
        const uint32_t stb = sb + (c & 1) * STG;
#pragma unroll
        for (int ks = 0; ks < 4; ks++) {
            uint32_t ah[2][4], al[2][4], bh[2][4], bl[2][4];
            uint32_t aoff = (wm * 32 + (lane & 15)) * GSTR + ks * 32 + (lane >> 4) * 16;
            uint32_t boff = (wn * 32 + (lane & 15)) * GSTR + ks * 32 + (lane >> 4) * 16;
#pragma unroll
            for (int mt = 0; mt < 2; mt++) {
                ldsm4(ah[mt], stb + aoff + mt * 16 * GSTR);
                ldsm4(al[mt], stb + SAL + aoff + mt * 16 * GSTR);
            }
#pragma unroll
            for (int bp = 0; bp < 2; bp++) {
                ldsm4(bh[bp], stb + SBH + boff + bp * 16 * GSTR);
                if (WSPLIT) ldsm4(bl[bp], stb + SBL + boff + bp * 16 * GSTR);
            }
#pragma unroll
            for (int mt = 0; mt < 2; mt++)
#pragma unroll
                for (int nt = 0; nt < 4; nt++) {
                    uint32_t h0 = bh[nt >> 1][nt & 1], h1 = bh[nt >> 1][(nt & 1) + 2];
                    mma16816(d[mt][nt], ah[mt], h0, h1);
                    mma16816(d[mt][nt], al[mt], h0, h1);
                    if (WSPLIT) {
                        uint32_t l0 = bl[nt >> 1][nt & 1], l1 = bl[nt >> 1][(nt & 1) + 2];
                        mma16816(d[mt][nt], ah[mt], l0, l1);
                    }
                }
        }
        __syncthreads();
        if (c + 2 < 8) pf(c + 2, c & 1);
        cp_commit();
    }

    // epilogue
#pragma unroll
    for (int mt = 0; mt < 2; mt++) {
        int r1 = row0 + wm * 32 + mt * 16 + (lane >> 2);
#pragma unroll
        for (int nt = 0; nt < 4; nt++) {
            int cc = col0 + wn * 32 + nt * 8 + (lane & 3) * 2;
            float b0 = bias[cc], b1 = bias[cc + 1];
            float v00 = d[mt][nt][0] + b0, v01 = d[mt][nt][1] + b1;
            float v10 = d[mt][nt][2] + b0, v11 = d[mt][nt][3] + b1;
            if (MODE == 0) {
                *(float2*)(out + (size_t)r1 * 512 + cc) = make_float2(v00, v01);
                *(float2*)(out + (size_t)(r1 + 8) * 512 + cc) = make_float2(v10, v11);
            } else {
                int hd = cc - col0;
#pragma unroll
                for (int rr = 0; rr < 2; rr++) {
                    int r = r1 + rr * 8;
                    float va0 = rr ? v10 : v00, va1 = rr ? v11 : v01;
                    int b = r >> 11, l = r & 2047;
                    size_t idx = (((size_t)(b * Hc + blockIdx.x)) * Lc + l) * HDc + hd;
                    if (MODE == 2) {
                        *(uint32_t*)(outh + idx) = packh2(va0, va1);
                    } else {
                        uint32_t hi = packh2(va0, va1);
                        __half2 hv = *(__half2*)&hi;
                        *(uint32_t*)(outh + idx) = hi;
                        *(uint32_t*)(outl + idx) =
                            packh2(va0 - __half2float(hv.x), va1 - __half2float(hv.y));
                    }
                }
            }
        }
    }
}

// ---------------------------------------------------------------------------
// Warp-MMA causal flash attention, fp16, 3-stage cp.async pipeline (stage 2
// overlays the dead Q-staging region), ONE barrier per tile.
// Grid (16, H, B), block 256 (8 warps), 2 CTAs/SM. K hi/lo (3-pass S),
// V single, P single (1-pass PV). exp2-domain softmax + vote rescale-skip.
// Output fp16 hi/lo ctx [B,L,D].
// ---------------------------------------------------------------------------
__global__ void __launch_bounds__(256, 2) flash_mma() {
    extern __shared__ char smem[];
    const uint32_t sb = smem_u32(smem);
    const int t = threadIdx.x, lane = t & 31, w = t >> 5;
    const int qt = 15 - blockIdx.x;  // heavy tiles first
    const int h = blockIdx.y, b = blockIdx.z;
    const size_t base = ((size_t)(b * Hc + h)) * Lc * HDc;
    const uint32_t SQH = 0, SQL = 18432;
    const uint32_t OKL = 9216, OV = 18432, STSZ = 27648, SST = 36864;

    const int njt = 2 * qt + 2;

    auto stage_base = [&](int jt) -> uint32_t {
        int s = jt % 3;
        return (s == 2) ? sb : sb + SST + (uint32_t)s * STSZ;
    };
    auto pf = [&](int jt) {
        uint32_t dstb = stage_base(jt);
#pragma unroll
        for (int i = 0; i < 2; i++) {
            int idx = i * 256 + t, r = idx >> 3, cb = (idx & 7) * 16, ce = (idx & 7) * 8;
            size_t g = base + (size_t)(jt * 64 + r) * HDc + ce;
            uint32_t d0 = dstb + r * GSTR + cb;
            cpasync16(d0,       g_Kh + g);
            cpasync16(d0 + OKL, g_Kl + g);
            cpasync16(d0 + OV,  g_V + g);
        }
    };

    pf(0); cp_commit();
    pf(1); cp_commit();

    // load Q tile (128 rows x 64 fp16, hi+lo)
#pragma unroll
    for (int i = 0; i < 4; i++) {
        int idx = i * 256 + t, r = idx >> 3, cb = (idx & 7) * 16, ce = (idx & 7) * 8;
        size_t g = base + (size_t)(qt * 128 + r) * HDc + ce;
        *(uint4*)(smem + SQH + r * GSTR + cb) = *(const uint4*)(g_Qh + g);
        *(uint4*)(smem + SQL + r * GSTR + cb) = *(const uint4*)(g_Ql + g);
    }
    __syncthreads();

    uint32_t qfh[4][4], qfl[4][4];
#pragma unroll
    for (int ks = 0; ks < 4; ks++) {
        uint32_t a = (w * 16 + (lane & 15)) * GSTR + ks * 32 + (lane >> 4) * 16;
        ldsm4(qfh[ks], sb + SQH + a);
        ldsm4(qfl[ks], sb + SQL + a);
    }

    float o[8][4];
#pragma unroll
    for (int i = 0; i < 8; i++)
#pragma unroll
        for (int e = 0; e < 4; e++) o[i][e] = 0.f;
    float m0 = -1e30f, m1 = -1e30f, l0 = 0.f, l1 = 0.f;
    const float SC2 = 0.125f * 1.44269504f;  // 1/sqrt(64) * log2(e)
    const int qlo = qt * 128 + w * 16;

    for (int jt = 0; jt < njt; jt++) {
        cp_wait1();
        __syncthreads();
        if (jt + 2 < njt) pf(jt + 2);
        cp_commit();

        const int J0 = jt * 64;
        const uint32_t stb = stage_base(jt);

        if (J0 <= qlo + 15) {
            // ---- S = Q K^T (K hi/lo, 3 logical passes) ----
            float s[8][4];
#pragma unroll
            for (int i = 0; i < 8; i++)
#pragma unroll
                for (int e = 0; e < 4; e++) s[i][e] = 0.f;
#pragma unroll
            for (int ks = 0; ks < 4; ks++) {
#pragma unroll
                for (int bp = 0; bp < 4; bp++) {
                    if (J0 + bp * 16 > qlo + 15) continue;  // fully masked cols
                    uint32_t off = (bp * 16 + (lane & 15)) * GSTR + ks * 32 + (lane >> 4) * 16;
                    uint32_t kh[4], kl[4];
                    ldsm4(kh, stb + off);
                    mma16816(s[bp * 2],     qfh[ks], kh[0], kh[2]);
                    mma16816(s[bp * 2 + 1], qfh[ks], kh[1], kh[3]);
                    mma16816(s[bp * 2],     qfl[ks], kh[0], kh[2]);
                    mma16816(s[bp * 2 + 1], qfl[ks], kh[1], kh[3]);
                    ldsm4(kl, stb + OKL + off);
                    mma16816(s[bp * 2],     qfh[ks], kl[0], kl[2]);
                    mma16816(s[bp * 2 + 1], qfh[ks], kl[1], kl[3]);
                }
            }

            // ---- scale (log2 domain) + causal mask ----
            if (J0 + 63 > qlo) {
                int q0 = qlo + (lane >> 2);
#pragma unroll
                for (int nt = 0; nt < 8; nt++) {
                    int kc = J0 + nt * 8 + (lane & 3) * 2;
                    s[nt][0] = (kc     <= q0)     ? s[nt][0] * SC2 : -1e30f;
                    s[nt][1] = (kc + 1 <= q0)     ? s[nt][1] * SC2 : -1e30f;
                    s[nt][2] = (kc     <= q0 + 8) ? s[nt][2] * SC2 : -1e30f;
                    s[nt][3] = (kc + 1 <= q0 + 8) ? s[nt][3] * SC2 : -1e30f;
                }
            } else {
#pragma unroll
                for (int nt = 0; nt < 8; nt++)
#pragma unroll
                    for (int e = 0; e < 4; e++) s[nt][e] *= SC2;
            }

            // ---- online softmax (base-2) ----
            float a0 = -1e30f, a1 = -1e30f;
#pragma unroll
            for (int nt = 0; nt < 8; nt++) {
                a0 = fmaxf(a0, fmaxf(s[nt][0], s[nt][1]));
                a1 = fmaxf(a1, fmaxf(s[nt][2], s[nt][3]));
            }
            a0 = fmaxf(a0, __shfl_xor_sync(0xffffffffu, a0, 1));
            a0 = fmaxf(a0, __shfl_xor_sync(0xffffffffu, a0, 2));
            a1 = fmaxf(a1, __shfl_xor_sync(0xffffffffu, a1, 1));
            a1 = fmaxf(a1, __shfl_xor_sync(0xffffffffu, a1, 2));
            float n0 = fmaxf(m0, a0), n1 = fmaxf(m1, a1);
            bool upd = (n0 > m0) || (n1 > m1);
            if (__any_sync(0xffffffffu, upd)) {
                float c0 = ex2(m0 - n0), c1 = ex2(m1 - n1);
                m0 = n0; m1 = n1; l0 *= c0; l1 *= c1;
#pragma unroll
                for (int nt = 0; nt < 8; nt++) {
                    o[nt][0] *= c0; o[nt][1] *= c0; o[nt][2] *= c1; o[nt][3] *= c1;
                }
            }

            // ---- P = exp2(S - m), single fp16; O += P V (1 pass) ----
#pragma unroll
            for (int ks = 0; ks < 4; ks++) {
                if (J0 + ks * 16 > qlo + 15) continue;  // p==0 there
                float p[8];
                p[0] = ex2(s[2 * ks][0] - m0);     p[1] = ex2(s[2 * ks][1] - m0);
                p[2] = ex2(s[2 * ks][2] - m1);     p[3] = ex2(s[2 * ks][3] - m1);
                p[4] = ex2(s[2 * ks + 1][0] - m0); p[5] = ex2(s[2 * ks + 1][1] - m0);
                p[6] = ex2(s[2 * ks + 1][2] - m1); p[7] = ex2(s[2 * ks + 1][3] - m1);
                l0 += p[0] + p[1] + p[4] + p[5];
                l1 += p[2] + p[3] + p[6] + p[7];
                uint32_t ph[4];
                ph[0] = packh2(p[0], p[1]);
                ph[1] = packh2(p[2], p[3]);
                ph[2] = packh2(p[4], p[5]);
                ph[3] = packh2(p[6], p[7]);
#pragma unroll
                for (int np = 0; np < 4; np++) {
                    uint32_t a = stb + OV + (ks * 16 + (lane & 15)) * GSTR + np * 32 + (lane >> 4) * 16;
                    uint32_t vh[4];
                    ldsm4t(vh, a);
                    mma16816(o[np * 2],     ph, vh[0], vh[1]);
                    mma16816(o[np * 2 + 1], ph, vh[2], vh[3]);
                }
            }
        }
    }

    // ---- finalize: write fp16 hi/lo ctx in [B,L,D] ----
    l0 += __shfl_xor_sync(0xffffffffu, l0, 1);
    l0 += __shfl_xor_sync(0xffffffffu, l0, 2);
    l1 += __shfl_xor_sync(0xffffffffu, l1, 1);
    l1 += __shfl_xor_sync(0xffffffffu, l1, 2);
    float i0 = 1.f / l0, i1 = 1.f / l1;
    int qrow = qt * 128 + w * 16 + (lane >> 2);
    size_t r0 = (size_t)b * Lc + qrow;
#pragma unroll
    for (int nt = 0; nt < 8; nt++) {
        int cc = h * HDc + nt * 8 + (lane & 3) * 2;
#pragma unroll
        for (int rr = 0; rr < 2; rr++) {
            float va0 = (rr ? o[nt][2] * i1 : o[nt][0] * i0);
            float va1 = (rr ? o[nt][3] * i1 : o[nt][1] * i0);
            size_t idx = (r0 + rr * 8) * Dc + cc;
            uint32_t hi = packh2(va0, va1);
            __half2 hv = *(__half2*)&hi;
            *(uint32_t*)(g_CXh + idx) = hi;
            *(uint32_t*)(g_CXl + idx) =
                packh2(va0 - __half2float(hv.x), va1 - __half2float(hv.y));
        }
    }
}

// ---------------------------------------------------------------------------
extern "C" void kernel_launch(void* const* d_in, const int* in_sizes, int n_in,
                              void* d_out, int out_size) {
    const float* q  = (const float*)d_in[0];
    const float* k  = (const float*)d_in[1];
    const float* v  = (const float*)d_in[2];
    const float* Wq = (const float*)d_in[4];
    const float* bq = (const float*)d_in[5];
    const float* Wk = (const float*)d_in[6];
    const float* bk = (const float*)d_in[7];
    const float* Wv = (const float*)d_in[8];
    const float* bv = (const float*)d_in[9];
    const float* Wo = (const float*)d_in[10];
    const float* bo = (const float*)d_in[11];
    float* out = (float*)d_out;

    __half *Qh, *Ql, *Kh, *Kl, *V, *CXh, *CXl, *Ah, *Al, *Wh, *Wl;
    cudaGetSymbolAddress((void**)&Qh, g_Qh);
    cudaGetSymbolAddress((void**)&Ql, g_Ql);
    cudaGetSymbolAddress((void**)&Kh, g_Kh);
    cudaGetSymbolAddress((void**)&Kl, g_Kl);
    cudaGetSymbolAddress((void**)&V,  g_V);
    cudaGetSymbolAddress((void**)&CXh, g_CXh);
    cudaGetSymbolAddress((void**)&CXl, g_CXl);
    cudaGetSymbolAddress((void**)&Ah, g_Ah);
    cudaGetSymbolAddress((void**)&Al, g_Al);
    cudaGetSymbolAddress((void**)&Wh, g_Wh);
    cudaGetSymbolAddress((void**)&Wl, g_Wl);

    const int gsmem = 2 * 55296;          // 110592
    const int fsmem = 36864 + 2 * 27648;  // 92160
    cudaFuncSetAttribute(gemm_mma<0>, cudaFuncAttributeMaxDynamicSharedMemorySize, gsmem);
    cudaFuncSetAttribute(gemm_mma<1>, cudaFuncAttributeMaxDynamicSharedMemorySize, gsmem);
    cudaFuncSetAttribute(gemm_mma<2>, cudaFuncAttributeMaxDynamicSharedMemorySize, gsmem);
    cudaFuncSetAttribute(flash_mma, cudaFuncAttributeMaxDynamicSharedMemorySize, fsmem);

    const int nX4 = BL * Dc / 4;   // 1048576
    const int nW4 = Dc * Dc / 4;   // 65536
    dim3 grd_gemm(Dc / 64, BL / 128);  // 8 x 64

    // convert all 4 weight matrices once
    cvt_hilo<<<nW4 / 256, 256>>>((const float4*)Wq, (uint2*)(Wh + 0 * Dc * Dc), (uint2*)(Wl + 0 * Dc * Dc), nW4);
    cvt_hilo<<<nW4 / 256, 256>>>((const float4*)Wk, (uint2*)(Wh + 1 * Dc * Dc), (uint2*)(Wl + 1 * Dc * Dc), nW4);
    cvt_hilo<<<nW4 / 256, 256>>>((const float4*)Wv, (uint2*)(Wh + 2 * Dc * Dc), (uint2*)(Wl + 2 * Dc * Dc), nW4);
    cvt_hilo<<<nW4 / 256, 256>>>((const float4*)Wo, (uint2*)(Wh + 3 * Dc * Dc), (uint2*)(Wl + 3 * Dc * Dc), nW4);

    // Q projection
    cvt_hilo<<<nX4 / 256, 256>>>((const float4*)q, (uint2*)Ah, (uint2*)Al, nX4);
    gemm_mma<1><<<grd_gemm, 256, gsmem>>>(Ah, Al, Wh + 0 * Dc * Dc, Wl + 0 * Dc * Dc, bq, nullptr, Qh, Ql);
    // K projection
    cvt_hilo<<<nX4 / 256, 256>>>((const float4*)k, (uint2*)Ah, (uint2*)Al, nX4);
    gemm_mma<1><<<grd_gemm, 256, gsmem>>>(Ah, Al, Wh + 1 * Dc * Dc, Wl + 1 * Dc * Dc, bk, nullptr, Kh, Kl);
    // V projection
    cvt_hilo<<<nX4 / 256, 256>>>((const float4*)v, (uint2*)Ah, (uint2*)Al, nX4);
    gemm_mma<2><<<grd_gemm, 256, gsmem>>>(Ah, Al, Wh + 2 * Dc * Dc, nullptr, bv, nullptr, V, nullptr);

    // attention
    dim3 grd_fa(Lc / 128, Hc, Bc);     // 16 x 8 x 4
    flash_mma<<<grd_fa, 256, fsmem>>>();

    // output projection
    gemm_mma<0><<<grd_gemm, 256, gsmem>>>(CXh, CXl, Wh + 3 * Dc * Dc, nullptr, bo, out, nullptr, nullptr);
}

// round 15
// speedup vs baseline: 1.4972x; 1.0457x over previous
#include <cuda_runtime.h>
#include <cuda_fp16.h>
#include <math.h>
#include <stdint.h>

#define Bc 4
#define Lc 2048
#define Dc 512
#define Hc 8
#define HDc 64
#define BL (Bc*Lc)

// ---------------- scratch (device globals; no allocation allowed) ----------
__device__ __half g_Qh[Bc*Hc*Lc*HDc];
__device__ __half g_Ql[Bc*Hc*Lc*HDc];
__device__ __half g_Kh[Bc*Hc*Lc*HDc];
__device__ __half g_Kl[Bc*Hc*Lc*HDc];
__device__ __half g_V [Bc*Hc*Lc*HDc];
__device__ __half g_CXh[BL*Dc];
__device__ __half g_CXl[BL*Dc];
__device__ __half g_A0h[BL*Dc];       // converted q activation
__device__ __half g_A0l[BL*Dc];
__device__ __half g_A1h[BL*Dc];       // converted k activation
__device__ __half g_A1l[BL*Dc];
__device__ __half g_A2h[BL*Dc];       // converted v activation
__device__ __half g_A2l[BL*Dc];
__device__ __half g_Wh[4*Dc*Dc];      // converted weights (q,k,v,o)
__device__ __half g_Wl[4*Dc*Dc];

// ---------------- helpers ---------------------------------------------------
__device__ __forceinline__ uint32_t smem_u32(const void* p) {
    uint32_t a;
    asm("{ .reg .u64 t; cvta.to.shared.u64 t, %1; cvt.u32.u64 %0, t; }"
        : "=r"(a) : "l"(p));
    return a;
}
__device__ __forceinline__ void ldsm4(uint32_t* r, uint32_t addr) {
    asm volatile("ldmatrix.sync.aligned.m8n8.x4.shared.b16 {%0,%1,%2,%3}, [%4];"
                 : "=r"(r[0]), "=r"(r[1]), "=r"(r[2]), "=r"(r[3]) : "r"(addr));
}
__device__ __forceinline__ void ldsm4t(uint32_t* r, uint32_t addr) {
    asm volatile("ldmatrix.sync.aligned.m8n8.x4.trans.shared.b16 {%0,%1,%2,%3}, [%4];"
                 : "=r"(r[0]), "=r"(r[1]), "=r"(r[2]), "=r"(r[3]) : "r"(addr));
}
__device__ __forceinline__ void mma16816(float* d, const uint32_t* a,
                                         uint32_t b0, uint32_t b1) {
    asm volatile("mma.sync.aligned.m16n8k16.row.col.f32.f16.f16.f32 "
                 "{%0,%1,%2,%3}, {%4,%5,%6,%7}, {%8,%9}, {%0,%1,%2,%3};"
                 : "+f"(d[0]), "+f"(d[1]), "+f"(d[2]), "+f"(d[3])
                 : "r"(a[0]), "r"(a[1]), "r"(a[2]), "r"(a[3]), "r"(b0), "r"(b1));
}
__device__ __forceinline__ uint32_t packh2(float a, float b) {
    __half2 v = __floats2half2_rn(a, b);
    return *(uint32_t*)&v;
}
__device__ __forceinline__ float ex2(float x) {
    float r;
    asm("ex2.approx.f32 %0, %1;" : "=f"(r) : "f"(x));
    return r;
}
__device__ __forceinline__ void cpasync16(uint32_t s, const void* g) {
    asm volatile("cp.async.cg.shared.global [%0], [%1], 16;" :: "r"(s), "l"(g) : "memory");
}
__device__ __forceinline__ void cp_commit() {
    asm volatile("cp.async.commit_group;" ::: "memory");
}
__device__ __forceinline__ void cp_wait1() {
    asm volatile("cp.async.wait_group 1;" ::: "memory");
}

// ---------------------------------------------------------------------------
// Fused fp32 -> fp16 hi/lo conversions.
// cvt_act: grid.y in {0,1,2} selects q/k/v -> A0/A1/A2
// cvt_w:   grid.y in {0..3} selects Wq/Wk/Wv/Wo -> Wh/Wl + y*Dc*Dc
// ---------------------------------------------------------------------------
__device__ __forceinline__ void cvt1(const float4* x, uint2* hi, uint2* lo, int i) {
    float4 v = x[i];
    uint2 h, l;
    h.x = packh2(v.x, v.y); h.y = packh2(v.z, v.w);
    __half2 a = *(__half2*)&h.x, b = *(__half2*)&h.y;
    l.x = packh2(v.x - __half2float(a.x), v.y - __half2float(a.y));
    l.y = packh2(v.z - __half2float(b.x), v.w - __half2float(b.y));
    hi[i] = h; lo[i] = l;
}
__global__ void cvt_act(const float4* __restrict__ q, const float4* __restrict__ k,
                        const float4* __restrict__ v) {
    int i = blockIdx.x * blockDim.x + threadIdx.x;
    int y = blockIdx.y;
    const float4* src = (y == 0) ? q : (y == 1) ? k : v;
    uint2* hi = (uint2*)((y == 0) ? g_A0h : (y == 1) ? g_A1h : g_A2h);
    uint2* lo = (uint2*)((y == 0) ? g_A0l : (y == 1) ? g_A1l : g_A2l);
    cvt1(src, hi, lo, i);
}
__global__ void cvt_w(const float4* __restrict__ wq, const float4* __restrict__ wk,
                      const float4* __restrict__ wv, const float4* __restrict__ wo) {
    int i = blockIdx.x * blockDim.x + threadIdx.x;
    int y = blockIdx.y;
    const float4* src = (y == 0) ? wq : (y == 1) ? wk : (y == 2) ? wv : wo;
    cvt1(src, (uint2*)(g_Wh + (size_t)y * Dc * Dc), (uint2*)(g_Wl + (size_t)y * Dc * Dc), i);
}

// ---------------------------------------------------------------------------
// Warp-MMA GEMM core (pure fp16 operands, cp.async double-buffered).
// wsplit: 3-pass (AhBh+AlBh+AhBl) vs 2-pass. Tile 128x64, BK=64, 8 warps.
// ---------------------------------------------------------------------------
#define GSTR 144  // smem row stride bytes (64 fp16 = 128B + 16 pad)
template<bool WSPLIT_CT, bool RUNTIME>
__device__ __forceinline__ void gemm_core(
    char* smem, uint32_t sb, int t, int lane, int wm, int wn,
    int row0, int col0, bool wsplit_rt,
    const __half* Ah, const __half* Al, const __half* Bh, const __half* Bl,
    float d[2][4][4]) {
    const uint32_t SAL = 18432, SBH = 36864, SBL = 46080, STG = 55296;
    const bool wsplit = RUNTIME ? wsplit_rt : WSPLIT_CT;

    auto pf = [&](int kc, int st) {
        const int k0 = kc * 64;
        uint32_t dstb = sb + st * STG;
#pragma unroll
        for (int i = 0; i < 4; i++) {
            int idx = i * 256 + t, r = idx >> 3, c = idx & 7;
            size_t g = (size_t)(row0 + r) * 512 + k0 + c * 8;
            uint32_t d0 = dstb + r * GSTR + c * 16;
            cpasync16(d0,       Ah + g);
            cpasync16(d0 + SAL, Al + g);
        }
#pragma unroll
        for (int i = 0; i < 2; i++) {
            int idx = i * 256 + t, r = idx >> 3, c = idx & 7;
            size_t g = (size_t)(col0 + r) * 512 + k0 + c * 8;
            uint32_t d0 = dstb + r * GSTR + c * 16;
            cpasync16(d0 + SBH, Bh + g);
            if (wsplit) cpasync16(d0 + SBL, Bl + g);
        }
    };

    pf(0, 0); cp_commit();
    pf(1, 1); cp_commit();

    for (int c = 0; c < 8; c++) {
        cp_wait1();
        __syncthreads();
        const uint32_t stb = sb + (c & 1) * STG;
#pragma unroll
        for (int ks = 0; ks < 4; ks++) {
            uint32_t ah[2][4], al[2][4], bh[2][4], bl[2][4];
            uint32_t aoff = (wm * 32 + (lane & 15)) * GSTR + ks * 32 + (lane >> 4) * 16;
            uint32_t boff = (wn * 32 + (lane & 15)) * GSTR + ks * 32 + (lane >> 4) * 16;
#pragma unroll
            for (int mt = 0; mt < 2; mt++) {
                ldsm4(ah[mt], stb + aoff + mt * 16 * GSTR);
                ldsm4(al[mt], stb + SAL + aoff + mt * 16 * GSTR);
            }
#pragma unroll
            for (int bp = 0; bp < 2; bp++) {
                ldsm4(bh[bp], stb + SBH + boff + bp * 16 * GSTR);
                if (wsplit) ldsm4(bl[bp], stb + SBL + boff + bp * 16 * GSTR);
            }
#pragma unroll
            for (int mt = 0; mt < 2; mt++)
#pragma unroll
                for (int nt = 0; nt < 4; nt++) {
                    uint32_t h0 = bh[nt >> 1][nt & 1], h1 = bh[nt >> 1][(nt & 1) + 2];
                    mma16816(d[mt][nt], ah[mt], h0, h1);
                    mma16816(d[mt][nt], al[mt], h0, h1);
                    if (wsplit) {
                        uint32_t l0 = bl[nt >> 1][nt & 1], l1 = bl[nt >> 1][(nt & 1) + 2];
                        mma16816(d[mt][nt], ah[mt], l0, l1);
                    }
                }
        }
        __syncthreads();
        if (c + 2 < 8) pf(c + 2, c & 1);
        cp_commit();
    }
}

// ---------------------------------------------------------------------------
// Fused QKV projection: grid (8, 64, 3). z selects activation/weight/bias/out.
// z in {0,1}: 3-pass, fp16 hi/lo out [B,H,L,HD]. z==2 (V): 2-pass, single out.
// ---------------------------------------------------------------------------
__global__ void __launch_bounds__(256, 2) gemm_qkv(
    const float* __restrict__ bq, const float* __restrict__ bk,
    const float* __restrict__ bv) {
    extern __shared__ char smem[];
    const uint32_t sb = smem_u32(smem);
    const int t = threadIdx.x, lane = t & 31, wid = t >> 5;
    const int wm = wid & 3, wn = wid >> 2;
    const int row0 = blockIdx.y * 128, col0 = blockIdx.x * 64;
    const int z = blockIdx.z;
    const bool wsplit = (z != 2);

    const __half* Ah = (z == 0) ? g_A0h : (z == 1) ? g_A1h : g_A2h;
    const __half* Al = (z == 0) ? g_A0l : (z == 1) ? g_A1l : g_A2l;
    const __half* Bh = g_Wh + (size_t)z * Dc * Dc;
    const __half* Bl = g_Wl + (size_t)z * Dc * Dc;
    const float* bias = (z == 0) ? bq : (z == 1) ? bk : bv;
    __half* outh = (z == 0) ? g_Qh : (z == 1) ? g_Kh : g_V;
    __half* outl = (z == 0) ? g_Ql : g_Kl;  // unused for z==2

    float d[2][4][4];
#pragma unroll
    for (int i = 0; i < 2; i++)
#pragma unroll
        for (int j = 0; j < 4; j++)
#pragma unroll
            for (int e = 0; e < 4; e++) d[i][j][e] = 0.f;

    gemm_core<false, true>(smem, sb, t, lane, wm, wn, row0, col0, wsplit,
                           Ah, Al, Bh, Bl, d);

    // epilogue: out in [B,H,L,HD], h = blockIdx.x
#pragma unroll
    for (int mt = 0; mt < 2; mt++) {
        int r1 = row0 + wm * 32 + mt * 16 + (lane >> 2);
#pragma unroll
        for (int nt = 0; nt < 4; nt++) {
            int cc = col0 + wn * 32 + nt * 8 + (lane & 3) * 2;
            float b0 = bias[cc], b1 = bias[cc + 1];
            float v00 = d[mt][nt][0] + b0, v01 = d[mt][nt][1] + b1;
            float v10 = d[mt][nt][2] + b0, v11 = d[mt][nt][3] + b1;
            int hd = cc - col0;
#pragma unroll
            for (int rr = 0; rr < 2; rr++) {
                int r = r1 + rr * 8;
                float va0 = rr ? v10 : v00, va1 = rr ? v11 : v01;
                int b = r >> 11, l = r & 2047;
                size_t idx = (((size_t)(b * Hc + blockIdx.x)) * Lc + l) * HDc + hd;
                if (z == 2) {
                    *(uint32_t*)(outh + idx) = packh2(va0, va1);
                } else {
                    uint32_t hi = packh2(va0, va1);
                    __half2 hv = *(__half2*)&hi;
                    *(uint32_t*)(outh + idx) = hi;
                    *(uint32_t*)(outl + idx) =
                        packh2(va0 - __half2float(hv.x), va1 - __half2float(hv.y));
                }
            }
        }
    }
}

// ---------------------------------------------------------------------------
// Output projection: A = ctx fp16 hi/lo, W single (2-pass), out fp32.
// ---------------------------------------------------------------------------
__global__ void __launch_bounds__(256, 2) gemm_out(
    const float* __restrict__ bias, float* __restrict__ out) {
    extern __shared__ char smem[];
    const uint32_t sb = smem_u32(smem);
    const int t = threadIdx.x, lane = t & 31, wid = t >> 5;
    const int wm = wid & 3, wn = wid >> 2;
    const int row0 = blockIdx.y * 128, col0 = blockIdx.x * 64;

    float d[2][4][4];
#pragma unroll
    for (int i = 0; i < 2; i++)
#pragma unroll
        for (int j = 0; j < 4; j++)
#pragma unroll
            for (int e = 0; e < 4; e++) d[i][j][e] = 0.f;

    gemm_core<false, false>(smem, sb, t, lane, wm, wn, row0, col0, false,
                            g_CXh, g_CXl, g_Wh + 3 * Dc * Dc, nullptr, d);

#pragma unroll
    for (int mt = 0; mt < 2; mt++) {
        int r1 = row0 + wm * 32 + mt * 16 + (lane >> 2);
#pragma unroll
        for (int nt = 0; nt < 4; nt++) {
            int cc = col0 + wn * 32 + nt * 8 + (lane & 3) * 2;
            float b0 = bias[cc], b1 = bias[cc + 1];
            *(float2*)(out + (size_t)r1 * 512 + cc) =
                make_float2(d[mt][nt][0] + b0, d[mt][nt][1] + b1);
            *(float2*)(out + (size_t)(r1 + 8) * 512 + cc) =
                make_float2(d[mt][nt][2] + b0, d[mt][nt][3] + b1);
        }
    }
}

// ---------------------------------------------------------------------------
// Warp-MMA causal flash attention (unchanged from R12): fp16, 3-stage
// cp.async pipeline, one barrier/tile, 2 CTAs/SM, K hi/lo 3-pass S,
// V single 1-pass PV, exp2 softmax. Output fp16 hi/lo ctx [B,L,D].
// ---------------------------------------------------------------------------
__global__ void __launch_bounds__(256, 2) flash_mma() {
    extern __shared__ char smem[];
    const uint32_t sb = smem_u32(smem);
    const int t = threadIdx.x, lane = t & 31, w = t >> 5;
    const int qt = 15 - blockIdx.x;  // heavy tiles first
    const int h = blockIdx.y, b = blockIdx.z;
    const size_t base = ((size_t)(b * Hc + h)) * Lc * HDc;
    const uint32_t SQH = 0, SQL = 18432;
    const uint32_t OKL = 9216, OV = 18432, STSZ = 27648, SST = 36864;

    const int njt = 2 * qt + 2;

    auto stage_base = [&](int jt) -> uint32_t {
        int s = jt % 3;
        return (s == 2) ? sb : sb + SST + (uint32_t)s * STSZ;
    };
    auto pf = [&](int jt) {
        uint32_t dstb = stage_base(jt);
#pragma unroll
        for (int i = 0; i < 2; i++) {
            int idx = i * 256 + t, r = idx >> 3, cb = (idx & 7) * 16, ce = (idx & 7) * 8;
            size_t g = base + (size_t)(jt * 64 + r) * HDc + ce;
            uint32_t d0 = dstb + r * GSTR + cb;
            cpasync16(d0,       g_Kh + g);
            cpasync16(d0 + OKL, g_Kl + g);
            cpasync16(d0 + OV,  g_V + g);
        }
    };

    pf(0); cp_commit();
    pf(1); cp_commit();

    // load Q tile (128 rows x 64 fp16, hi+lo)
#pragma unroll
    for (int i = 0; i < 4; i++) {
        int idx = i * 256 + t, r = idx >> 3, cb = (idx & 7) * 16, ce = (idx & 7) * 8;
        size_t g = base + (size_t)(qt * 128 + r) * HDc + ce;
        *(uint4*)(smem + SQH + r * GSTR + cb) = *(const uint4*)(g_Qh + g);
        *(uint4*)(smem + SQL + r * GSTR + cb) = *(const uint4*)(g_Ql + g);
    }
    __syncthreads();

    uint32_t qfh[4][4], qfl[4][4];
#pragma unroll
    for (int ks = 0; ks < 4; ks++) {
        uint32_t a = (w * 16 + (lane & 15)) * GSTR + ks * 32 + (lane >> 4) * 16;
        ldsm4(qfh[ks], sb + SQH + a);
        ldsm4(qfl[ks], sb + SQL + a);
    }

    float o[8][4];
#pragma unroll
    for (int i = 0; i < 8; i++)
#pragma unroll
        for (int e = 0; e < 4; e++) o[i][e] = 0.f;
    float m0 = -1e30f, m1 = -1e30f, l0 = 0.f, l1 = 0.f;
    const float SC2 = 0.125f * 1.44269504f;  // 1/sqrt(64) * log2(e)
    const int qlo = qt * 128 + w * 16;

    for (int jt = 0; jt < njt; jt++) {
        cp_wait1();
        __syncthreads();
        if (jt + 2 < njt) pf(jt + 2);
        cp_commit();

        const int J0 = jt * 64;
        const uint32_t stb = stage_base(jt);

        if (J0 <= qlo + 15) {
            float s[8][4];
#pragma unroll
            for (int i = 0; i < 8; i++)
#pragma unroll
                for (int e = 0; e < 4; e++) s[i][e] = 0.f;
#pragma unroll
            for (int ks = 0; ks < 4; ks++) {
#pragma unroll
                for (int bp = 0; bp < 4; bp++) {
                    if (J0 + bp * 16 > qlo + 15) continue;
                    uint32_t off = (bp * 16 + (lane & 15)) * GSTR + ks * 32 + (lane >> 4) * 16;
                    uint32_t kh[4], kl[4];
                    ldsm4(kh, stb + off);
                    mma16816(s[bp * 2],     qfh[ks], kh[0], kh[2]);
                    mma16816(s[bp * 2 + 1], qfh[ks], kh[1], kh[3]);
                    mma16816(s[bp * 2],     qfl[ks], kh[0], kh[2]);
                    mma16816(s[bp * 2 + 1], qfl[ks], kh[1], kh[3]);
                    ldsm4(kl, stb + OKL + off);
                    mma16816(s[bp * 2],     qfh[ks], kl[0], kl[2]);
                    mma16816(s[bp * 2 + 1], qfh[ks], kl[1], kl[3]);
                }
            }

            if (J0 + 63 > qlo) {
                int q0 = qlo + (lane >> 2);
#pragma unroll
                for (int nt = 0; nt < 8; nt++) {
                    int kc = J0 + nt * 8 + (lane & 3) * 2;
                    s[nt][0] = (kc     <= q0)     ? s[nt][0] * SC2 : -1e30f;
                    s[nt][1] = (kc + 1 <= q0)     ? s[nt][1] * SC2 : -1e30f;
                    s[nt][2] = (kc     <= q0 + 8) ? s[nt][2] * SC2 : -1e30f;
                    s[nt][3] = (kc + 1 <= q0 + 8) ? s[nt][3] * SC2 : -1e30f;
                }
            } else {
#pragma unroll
                for (int nt = 0; nt < 8; nt++)
#pragma unroll
                    for (int e = 0; e < 4; e++) s[nt][e] *= SC2;
            }

            float a0 = -1e30f, a1 = -1e30f;
#pragma unroll
            for (int nt = 0; nt < 8; nt++) {
                a0 = fmaxf(a0, fmaxf(s[nt][0], s[nt][1]));
                a1 = fmaxf(a1, fmaxf(s[nt][2], s[nt][3]));
            }
            a0 = fmaxf(a0, __shfl_xor_sync(0xffffffffu, a0, 1));
            a0 = fmaxf(a0, __shfl_xor_sync(0xffffffffu, a0, 2));
            a1 = fmaxf(a1, __shfl_xor_sync(0xffffffffu, a1, 1));
            a1 = fmaxf(a1, __shfl_xor_sync(0xffffffffu, a1, 2));
            float n0 = fmaxf(m0, a0), n1 = fmaxf(m1, a1);
            bool upd = (n0 > m0) || (n1 > m1);
            if (__any_sync(0xffffffffu, upd)) {
                float c0 = ex2(m0 - n0), c1 = ex2(m1 - n1);
                m0 = n0; m1 = n1; l0 *= c0; l1 *= c1;
#pragma unroll
                for (int nt = 0; nt < 8; nt++) {
                    o[nt][0] *= c0; o[nt][1] *= c0; o[nt][2] *= c1; o[nt][3] *= c1;
                }
            }

#pragma unroll
            for (int ks = 0; ks < 4; ks++) {
                if (J0 + ks * 16 > qlo + 15) continue;
                float p[8];
                p[0] = ex2(s[2 * ks][0] - m0);     p[1] = ex2(s[2 * ks][1] - m0);
                p[2] = ex2(s[2 * ks][2] - m1);     p[3] = ex2(s[2 * ks][3] - m1);
                p[4] = ex2(s[2 * ks + 1][0] - m0); p[5] = ex2(s[2 * ks + 1][1] - m0);
                p[6] = ex2(s[2 * ks + 1][2] - m1); p[7] = ex2(s[2 * ks + 1][3] - m1);
                l0 += p[0] + p[1] + p[4] + p[5];
                l1 += p[2] + p[3] + p[6] + p[7];
                uint32_t ph[4];
                ph[0] = packh2(p[0], p[1]);
                ph[1] = packh2(p[2], p[3]);
                ph[2] = packh2(p[4], p[5]);
                ph[3] = packh2(p[6], p[7]);
#pragma unroll
                for (int np = 0; np < 4; np++) {
                    uint32_t a = stb + OV + (ks * 16 + (lane & 15)) * GSTR + np * 32 + (lane >> 4) * 16;
                    uint32_t vh[4];
                    ldsm4t(vh, a);
                    mma16816(o[np * 2],     ph, vh[0], vh[1]);
                    mma16816(o[np * 2 + 1], ph, vh[2], vh[3]);
                }
            }
        }
    }

    // ---- finalize: write fp16 hi/lo ctx in [B,L,D] ----
    l0 += __shfl_xor_sync(0xffffffffu, l0, 1);
    l0 += __shfl_xor_sync(0xffffffffu, l0, 2);
    l1 += __shfl_xor_sync(0xffffffffu, l1, 1);
    l1 += __shfl_xor_sync(0xffffffffu, l1, 2);
    float i0 = 1.f / l0, i1 = 1.f / l1;
    int qrow = qt * 128 + w * 16 + (lane >> 2);
    size_t r0 = (size_t)b * Lc + qrow;
#pragma unroll
    for (int nt = 0; nt < 8; nt++) {
        int cc = h * HDc + nt * 8 + (lane & 3) * 2;
#pragma unroll
        for (int rr = 0; rr < 2; rr++) {
            float va0 = (rr ? o[nt][2] * i1 : o[nt][0] * i0);
            float va1 = (rr ? o[nt][3] * i1 : o[nt][1] * i0);
            size_t idx = (r0 + rr * 8) * Dc + cc;
            uint32_t hi = packh2(va0, va1);
            __half2 hv = *(__half2*)&hi;
            *(uint32_t*)(g_CXh + idx) = hi;
            *(uint32_t*)(g_CXl + idx) =
                packh2(va0 - __half2float(hv.x), va1 - __half2float(hv.y));
        }
    }
}

// ---------------------------------------------------------------------------
extern "C" void kernel_launch(void* const* d_in, const int* in_sizes, int n_in,
                              void* d_out, int out_size) {
    const float* q  = (const float*)d_in[0];
    const float* k  = (const float*)d_in[1];
    const float* v  = (const float*)d_in[2];
    const float* Wq = (const float*)d_in[4];
    const float* bq = (const float*)d_in[5];
    const float* Wk = (const float*)d_in[6];
    const float* bk = (const float*)d_in[7];
    const float* Wv = (const float*)d_in[8];
    const float* bv = (const float*)d_in[9];
    const float* Wo = (const float*)d_in[10];
    const float* bo = (const float*)d_in[11];
    float* out = (float*)d_out;

    const int gsmem = 2 * 55296;          // 110592
    const int fsmem = 36864 + 2 * 27648;  // 92160
    cudaFuncSetAttribute(gemm_qkv, cudaFuncAttributeMaxDynamicSharedMemorySize, gsmem);
    cudaFuncSetAttribute(gemm_out, cudaFuncAttributeMaxDynamicSharedMemorySize, gsmem);
    cudaFuncSetAttribute(flash_mma, cudaFuncAttributeMaxDynamicSharedMemorySize, fsmem);

    const int nX4 = BL * Dc / 4;   // 1048576
    const int nW4 = Dc * Dc / 4;   // 65536

    // fused conversions: 2 launches total
    dim3 grd_cw(nW4 / 256, 4);
    cvt_w<<<grd_cw, 256>>>((const float4*)Wq, (const float4*)Wk,
                           (const float4*)Wv, (const float4*)Wo);
    dim3 grd_ca(nX4 / 256, 3);
    cvt_act<<<grd_ca, 256>>>((const float4*)q, (const float4*)k, (const float4*)v);

    // fused QKV projection: one launch, 1536 CTAs
    dim3 grd_qkv(Dc / 64, BL / 128, 3);
    gemm_qkv<<<grd_qkv, 256, gsmem>>>(bq, bk, bv);

    // attention
    dim3 grd_fa(Lc / 128, Hc, Bc);     // 16 x 8 x 4
    flash_mma<<<grd_fa, 256, fsmem>>>();

    // output projection
    dim3 grd_o(Dc / 64, BL / 128);
    gemm_out<<<grd_o, 256, gsmem>>>(bo, out);
}

// round 16
// speedup vs baseline: 1.8690x; 1.2483x over previous
#include <cuda_runtime.h>
#include <cuda_fp16.h>
#include <math.h>
#include <stdint.h>

#define Bc 4
#define Lc 2048
#define Dc 512
#define Hc 8
#define HDc 64
#define BL (Bc*Lc)

// ---------------- scratch (device globals; no allocation allowed) ----------
__device__ __half g_Qh[Bc*Hc*Lc*HDc];
__device__ __half g_Ql[Bc*Hc*Lc*HDc];
__device__ __half g_K [Bc*Hc*Lc*HDc];
__device__ __half g_V [Bc*Hc*Lc*HDc];
__device__ __half g_CXh[BL*Dc];
__device__ __half g_CXl[BL*Dc];
__device__ __half g_A0h[BL*Dc];       // converted q activation
__device__ __half g_A0l[BL*Dc];
__device__ __half g_A1h[BL*Dc];       // converted k activation
__device__ __half g_A1l[BL*Dc];
__device__ __half g_A2h[BL*Dc];       // converted v activation
__device__ __half g_A2l[BL*Dc];
__device__ __half g_Wh[4*Dc*Dc];      // converted weights (q,k,v,o), single fp16

// ---------------- helpers ---------------------------------------------------
__device__ __forceinline__ uint32_t smem_u32(const void* p) {
    uint32_t a;
    asm("{ .reg .u64 t; cvta.to.shared.u64 t, %1; cvt.u32.u64 %0, t; }"
        : "=r"(a) : "l"(p));
    return a;
}
__device__ __forceinline__ void ldsm4(uint32_t* r, uint32_t addr) {
    asm volatile("ldmatrix.sync.aligned.m8n8.x4.shared.b16 {%0,%1,%2,%3}, [%4];"
                 : "=r"(r[0]), "=r"(r[1]), "=r"(r[2]), "=r"(r[3]) : "r"(addr));
}
__device__ __forceinline__ void ldsm4t(uint32_t* r, uint32_t addr) {
    asm volatile("ldmatrix.sync.aligned.m8n8.x4.trans.shared.b16 {%0,%1,%2,%3}, [%4];"
                 : "=r"(r[0]), "=r"(r[1]), "=r"(r[2]), "=r"(r[3]) : "r"(addr));
}
__device__ __forceinline__ void mma16816(float* d, const uint32_t* a,
                                         uint32_t b0, uint32_t b1) {
    asm volatile("mma.sync.aligned.m16n8k16.row.col.f32.f16.f16.f32 "
                 "{%0,%1,%2,%3}, {%4,%5,%6,%7}, {%8,%9}, {%0,%1,%2,%3};"
                 : "+f"(d[0]), "+f"(d[1]), "+f"(d[2]), "+f"(d[3])
                 : "r"(a[0]), "r"(a[1]), "r"(a[2]), "r"(a[3]), "r"(b0), "r"(b1));
}
__device__ __forceinline__ uint32_t packh2(float a, float b) {
    __half2 v = __floats2half2_rn(a, b);
    return *(uint32_t*)&v;
}
__device__ __forceinline__ float ex2(float x) {
    float r;
    asm("ex2.approx.f32 %0, %1;" : "=f"(r) : "f"(x));
    return r;
}
__device__ __forceinline__ void cpasync16(uint32_t s, const void* g) {
    asm volatile("cp.async.cg.shared.global [%0], [%1], 16;" :: "r"(s), "l"(g) : "memory");
}
__device__ __forceinline__ void cp_commit() {
    asm volatile("cp.async.commit_group;" ::: "memory");
}
__device__ __forceinline__ void cp_wait1() {
    asm volatile("cp.async.wait_group 1;" ::: "memory");
}

// ---------------------------------------------------------------------------
// Fused conversions.
// cvt_act: grid.y {0,1,2} selects q/k/v -> A{0,1,2} hi/lo
// cvt_w:   grid.y {0..3} selects Wq/Wk/Wv/Wo -> Wh + y*Dc*Dc (single fp16)
// ---------------------------------------------------------------------------
__global__ void cvt_act(const float4* __restrict__ q, const float4* __restrict__ k,
                        const float4* __restrict__ v) {
    int i = blockIdx.x * blockDim.x + threadIdx.x;
    int y = blockIdx.y;
    const float4* src = (y == 0) ? q : (y == 1) ? k : v;
    uint2* hi = (uint2*)((y == 0) ? g_A0h : (y == 1) ? g_A1h : g_A2h);
    uint2* lo = (uint2*)((y == 0) ? g_A0l : (y == 1) ? g_A1l : g_A2l);
    float4 x = src[i];
    uint2 h, l;
    h.x = packh2(x.x, x.y); h.y = packh2(x.z, x.w);
    __half2 a = *(__half2*)&h.x, b = *(__half2*)&h.y;
    l.x = packh2(x.x - __half2float(a.x), x.y - __half2float(a.y));
    l.y = packh2(x.z - __half2float(b.x), x.w - __half2float(b.y));
    hi[i] = h; lo[i] = l;
}
__global__ void cvt_w(const float4* __restrict__ wq, const float4* __restrict__ wk,
                      const float4* __restrict__ wv, const float4* __restrict__ wo) {
    int i = blockIdx.x * blockDim.x + threadIdx.x;
    int y = blockIdx.y;
    const float4* src = (y == 0) ? wq : (y == 1) ? wk : (y == 2) ? wv : wo;
    float4 x = src[i];
    uint2 h;
    h.x = packh2(x.x, x.y); h.y = packh2(x.z, x.w);
    ((uint2*)(g_Wh + (size_t)y * Dc * Dc))[i] = h;
}

// ---------------------------------------------------------------------------
// Warp-MMA GEMM core: uniform 2-pass (AhBh + AlBh), A hi/lo, B single fp16.
// cp.async double-buffered. Tile 128x64, BK=64, 8 warps, 2 CTAs/SM.
// ---------------------------------------------------------------------------
#define GSTR 144  // smem row stride bytes (64 fp16 = 128B + 16 pad)
__device__ __forceinline__ void gemm_core(
    uint32_t sb, int t, int lane, int wm, int wn, int row0, int col0,
    const __half* Ah, const __half* Al, const __half* Bh,
    float d[2][4][4]) {
    const uint32_t SAL = 18432, SBH = 36864, STG = 46080;

    auto pf = [&](int kc, int st) {
        const int k0 = kc * 64;
        uint32_t dstb = sb + st * STG;
#pragma unroll
        for (int i = 0; i < 4; i++) {
            int idx = i * 256 + t, r = idx >> 3, c = idx & 7;
            size_t g = (size_t)(row0 + r) * 512 + k0 + c * 8;
            uint32_t d0 = dstb + r * GSTR + c * 16;
            cpasync16(d0,       Ah + g);
            cpasync16(d0 + SAL, Al + g);
        }
#pragma unroll
        for (int i = 0; i < 2; i++) {
            int idx = i * 256 + t, r = idx >> 3, c = idx & 7;
            size_t g = (size_t)(col0 + r) * 512 + k0 + c * 8;
            cpasync16(dstb + SBH + r * GSTR + c * 16, Bh + g);
        }
    };

    pf(0, 0); cp_commit();
    pf(1, 1); cp_commit();

    for (int c = 0; c < 8; c++) {
        cp_wait1();
        __syncthreads();
        const uint32_t stb = sb + (c & 1) * STG;
#pragma unroll
        for (int ks = 0; ks < 4; ks++) {
            uint32_t ah[2][4], al[2][4], bh[2][4];
            uint32_t aoff = (wm * 32 + (lane & 15)) * GSTR + ks * 32 + (lane >> 4) * 16;
            uint32_t boff = (wn * 32 + (lane & 15)) * GSTR + ks * 32 + (lane >> 4) * 16;
#pragma unroll
            for (int mt = 0; mt < 2; mt++) {
                ldsm4(ah[mt], stb + aoff + mt * 16 * GSTR);
                ldsm4(al[mt], stb + SAL + aoff + mt * 16 * GSTR);
            }
#pragma unroll
            for (int bp = 0; bp < 2; bp++)
                ldsm4(bh[bp], stb + SBH + boff + bp * 16 * GSTR);
#pragma unroll
            for (int mt = 0; mt < 2; mt++)
#pragma unroll
                for (int nt = 0; nt < 4; nt++) {
                    uint32_t h0 = bh[nt >> 1][nt & 1], h1 = bh[nt >> 1][(nt & 1) + 2];
                    mma16816(d[mt][nt], ah[mt], h0, h1);
                    mma16816(d[mt][nt], al[mt], h0, h1);
                }
        }
        __syncthreads();
        if (c + 2 < 8) pf(c + 2, c & 1);
        cp_commit();
    }
}

// ---------------------------------------------------------------------------
// Fused QKV projection: grid (8, 64, 3). z selects activation/weight/bias/out.
// z==0 (Q): out fp16 hi/lo. z==1 (K), z==2 (V): out single fp16. [B,H,L,HD].
// ---------------------------------------------------------------------------
__global__ void __launch_bounds__(256, 2) gemm_qkv(
    const float* __restrict__ bq, const float* __restrict__ bk,
    const float* __restrict__ bv) {
    extern __shared__ char smem[];
    const uint32_t sb = smem_u32(smem);
    const int t = threadIdx.x, lane = t & 31, wid = t >> 5;
    const int wm = wid & 3, wn = wid >> 2;
    const int row0 = blockIdx.y * 128, col0 = blockIdx.x * 64;
    const int z = blockIdx.z;

    const __half* Ah = (z == 0) ? g_A0h : (z == 1) ? g_A1h : g_A2h;
    const __half* Al = (z == 0) ? g_A0l : (z == 1) ? g_A1l : g_A2l;
    const __half* Bh = g_Wh + (size_t)z * Dc * Dc;
    const float* bias = (z == 0) ? bq : (z == 1) ? bk : bv;
    __half* outh = (z == 0) ? g_Qh : (z == 1) ? g_K : g_V;

    float d[2][4][4];
#pragma unroll
    for (int i = 0; i < 2; i++)
#pragma unroll
        for (int j = 0; j < 4; j++)
#pragma unroll
            for (int e = 0; e < 4; e++) d[i][j][e] = 0.f;

    gemm_core(sb, t, lane, wm, wn, row0, col0, Ah, Al, Bh, d);

#pragma unroll
    for (int mt = 0; mt < 2; mt++) {
        int r1 = row0 + wm * 32 + mt * 16 + (lane >> 2);
#pragma unroll
        for (int nt = 0; nt < 4; nt++) {
            int cc = col0 + wn * 32 + nt * 8 + (lane & 3) * 2;
            float b0 = bias[cc], b1 = bias[cc + 1];
            float v00 = d[mt][nt][0] + b0, v01 = d[mt][nt][1] + b1;
            float v10 = d[mt][nt][2] + b0, v11 = d[mt][nt][3] + b1;
            int hd = cc - col0;
#pragma unroll
            for (int rr = 0; rr < 2; rr++) {
                int r = r1 + rr * 8;
                float va0 = rr ? v10 : v00, va1 = rr ? v11 : v01;
                int b = r >> 11, l = r & 2047;
                size_t idx = (((size_t)(b * Hc + blockIdx.x)) * Lc + l) * HDc + hd;
                uint32_t hi = packh2(va0, va1);
                *(uint32_t*)(outh + idx) = hi;
                if (z == 0) {
                    __half2 hv = *(__half2*)&hi;
                    *(uint32_t*)(g_Ql + idx) =
                        packh2(va0 - __half2float(hv.x), va1 - __half2float(hv.y));
                }
            }
        }
    }
}

// ---------------------------------------------------------------------------
// Output projection: A = ctx fp16 hi/lo, W single (2-pass), out fp32.
// ---------------------------------------------------------------------------
__global__ void __launch_bounds__(256, 2) gemm_out(
    const float* __restrict__ bias, float* __restrict__ out) {
    extern __shared__ char smem[];
    const uint32_t sb = smem_u32(smem);
    const int t = threadIdx.x, lane = t & 31, wid = t >> 5;
    const int wm = wid & 3, wn = wid >> 2;
    const int row0 = blockIdx.y * 128, col0 = blockIdx.x * 64;

    float d[2][4][4];
#pragma unroll
    for (int i = 0; i < 2; i++)
#pragma unroll
        for (int j = 0; j < 4; j++)
#pragma unroll
            for (int e = 0; e < 4; e++) d[i][j][e] = 0.f;

    gemm_core(sb, t, lane, wm, wn, row0, col0, g_CXh, g_CXl, g_Wh + 3 * Dc * Dc, d);

#pragma unroll
    for (int mt = 0; mt < 2; mt++) {
        int r1 = row0 + wm * 32 + mt * 16 + (lane >> 2);
#pragma unroll
        for (int nt = 0; nt < 4; nt++) {
            int cc = col0 + wn * 32 + nt * 8 + (lane & 3) * 2;
            float b0 = bias[cc], b1 = bias[cc + 1];
            *(float2*)(out + (size_t)r1 * 512 + cc) =
                make_float2(d[mt][nt][0] + b0, d[mt][nt][1] + b1);
            *(float2*)(out + (size_t)(r1 + 8) * 512 + cc) =
                make_float2(d[mt][nt][2] + b0, d[mt][nt][3] + b1);
        }
    }
}

// ---------------------------------------------------------------------------
// Warp-MMA causal flash attention. fp16, 3-stage cp.async pipeline (K+V
// single-precision stages, 18.4KB each), one barrier/tile, 2 CTAs/SM.
// S = QhK + QlK (2-pass, Q split exact, K single). PV 1-pass.
// exp2 softmax + vote rescale-skip. Output fp16 hi/lo ctx [B,L,D].
// ---------------------------------------------------------------------------
__global__ void __launch_bounds__(256, 2) flash_mma() {
    extern __shared__ char smem[];
    const uint32_t sb = smem_u32(smem);
    const int t = threadIdx.x, lane = t & 31, w = t >> 5;
    const int qt = 15 - blockIdx.x;  // heavy tiles first
    const int h = blockIdx.y, b = blockIdx.z;
    const size_t base = ((size_t)(b * Hc + h)) * Lc * HDc;
    const uint32_t SQH = 0, SQL = 18432;
    const uint32_t OV = 9216, STSZ = 18432, SST = 36864;

    const int njt = 2 * qt + 2;

    auto stage_base = [&](int jt) -> uint32_t {
        return sb + SST + (uint32_t)(jt % 3) * STSZ;
    };
    auto pf = [&](int jt) {
        uint32_t dstb = stage_base(jt);
#pragma unroll
        for (int i = 0; i < 2; i++) {
            int idx = i * 256 + t, r = idx >> 3, cb = (idx & 7) * 16, ce = (idx & 7) * 8;
            size_t g = base + (size_t)(jt * 64 + r) * HDc + ce;
            uint32_t d0 = dstb + r * GSTR + cb;
            cpasync16(d0,      g_K + g);
            cpasync16(d0 + OV, g_V + g);
        }
    };

    pf(0); cp_commit();
    pf(1); cp_commit();

    // load Q tile (128 rows x 64 fp16, hi+lo)
#pragma unroll
    for (int i = 0; i < 4; i++) {
        int idx = i * 256 + t, r = idx >> 3, cb = (idx & 7) * 16, ce = (idx & 7) * 8;
        size_t g = base + (size_t)(qt * 128 + r) * HDc + ce;
        *(uint4*)(smem + SQH + r * GSTR + cb) = *(const uint4*)(g_Qh + g);
        *(uint4*)(smem + SQL + r * GSTR + cb) = *(const uint4*)(g_Ql + g);
    }
    __syncthreads();

    uint32_t qfh[4][4], qfl[4][4];
#pragma unroll
    for (int ks = 0; ks < 4; ks++) {
        uint32_t a = (w * 16 + (lane & 15)) * GSTR + ks * 32 + (lane >> 4) * 16;
        ldsm4(qfh[ks], sb + SQH + a);
        ldsm4(qfl[ks], sb + SQL + a);
    }

    float o[8][4];
#pragma unroll
    for (int i = 0; i < 8; i++)
#pragma unroll
        for (int e = 0; e < 4; e++) o[i][e] = 0.f;
    float m0 = -1e30f, m1 = -1e30f, l0 = 0.f, l1 = 0.f;
    const float SC2 = 0.125f * 1.44269504f;  // 1/sqrt(64) * log2(e)
    const int qlo = qt * 128 + w * 16;

    for (int jt = 0; jt < njt; jt++) {
        cp_wait1();
        __syncthreads();
        if (jt + 2 < njt) pf(jt + 2);
        cp_commit();

        const int J0 = jt * 64;
        const uint32_t stb = stage_base(jt);

        if (J0 <= qlo + 15) {
            // ---- S = Q K^T (Q hi/lo 2-pass, K single) ----
            float s[8][4];
#pragma unroll
            for (int i = 0; i < 8; i++)
#pragma unroll
                for (int e = 0; e < 4; e++) s[i][e] = 0.f;
#pragma unroll
            for (int ks = 0; ks < 4; ks++) {
#pragma unroll
                for (int bp = 0; bp < 4; bp++) {
                    if (J0 + bp * 16 > qlo + 15) continue;
                    uint32_t off = (bp * 16 + (lane & 15)) * GSTR + ks * 32 + (lane >> 4) * 16;
                    uint32_t kh[4];
                    ldsm4(kh, stb + off);
                    mma16816(s[bp * 2],     qfh[ks], kh[0], kh[2]);
                    mma16816(s[bp * 2 + 1], qfh[ks], kh[1], kh[3]);
                    mma16816(s[bp * 2],     qfl[ks], kh[0], kh[2]);
                    mma16816(s[bp * 2 + 1], qfl[ks], kh[1], kh[3]);
                }
            }

            // ---- scale (log2 domain) + causal mask ----
            if (J0 + 63 > qlo) {
                int q0 = qlo + (lane >> 2);
#pragma unroll
                for (int nt = 0; nt < 8; nt++) {
                    int kc = J0 + nt * 8 + (lane & 3) * 2;
                    s[nt][0] = (kc     <= q0)     ? s[nt][0] * SC2 : -1e30f;
                    s[nt][1] = (kc + 1 <= q0)     ? s[nt][1] * SC2 : -1e30f;
                    s[nt][2] = (kc     <= q0 + 8) ? s[nt][2] * SC2 : -1e30f;
                    s[nt][3] = (kc + 1 <= q0 + 8) ? s[nt][3] * SC2 : -1e30f;
                }
            } else {
#pragma unroll
                for (int nt = 0; nt < 8; nt++)
#pragma unroll
                    for (int e = 0; e < 4; e++) s[nt][e] *= SC2;
            }

            // ---- online softmax (base-2) ----
            float a0 = -1e30f, a1 = -1e30f;
#pragma unroll
            for (int nt = 0; nt < 8; nt++) {
                a0 = fmaxf(a0, fmaxf(s[nt][0], s[nt][1]));
                a1 = fmaxf(a1, fmaxf(s[nt][2], s[nt][3]));
            }
            a0 = fmaxf(a0, __shfl_xor_sync(0xffffffffu, a0, 1));
            a0 = fmaxf(a0, __shfl_xor_sync(0xffffffffu, a0, 2));
            a1 = fmaxf(a1, __shfl_xor_sync(0xffffffffu, a1, 1));
            a1 = fmaxf(a1, __shfl_xor_sync(0xffffffffu, a1, 2));
            float n0 = fmaxf(m0, a0), n1 = fmaxf(m1, a1);
            bool upd = (n0 > m0) || (n1 > m1);
            if (__any_sync(0xffffffffu, upd)) {
                float c0 = ex2(m0 - n0), c1 = ex2(m1 - n1);
                m0 = n0; m1 = n1; l0 *= c0; l1 *= c1;
#pragma unroll
                for (int nt = 0; nt < 8; nt++) {
                    o[nt][0] *= c0; o[nt][1] *= c0; o[nt][2] *= c1; o[nt][3] *= c1;
                }
            }

            // ---- P = exp2(S - m), single fp16; O += P V (1 pass) ----
#pragma unroll
            for (int ks = 0; ks < 4; ks++) {
                if (J0 + ks * 16 > qlo + 15) continue;
                float p[8];
                p[0] = ex2(s[2 * ks][0] - m0);     p[1] = ex2(s[2 * ks][1] - m0);
                p[2] = ex2(s[2 * ks][2] - m1);     p[3] = ex2(s[2 * ks][3] - m1);
                p[4] = ex2(s[2 * ks + 1][0] - m0); p[5] = ex2(s[2 * ks + 1][1] - m0);
                p[6] = ex2(s[2 * ks + 1][2] - m1); p[7] = ex2(s[2 * ks + 1][3] - m1);
                l0 += p[0] + p[1] + p[4] + p[5];
                l1 += p[2] + p[3] + p[6] + p[7];
                uint32_t ph[4];
                ph[0] = packh2(p[0], p[1]);
                ph[1] = packh2(p[2], p[3]);
                ph[2] = packh2(p[4], p[5]);
                ph[3] = packh2(p[6], p[7]);
#pragma unroll
                for (int np = 0; np < 4; np++) {
                    uint32_t a = stb + OV + (ks * 16 + (lane & 15)) * GSTR + np * 32 + (lane >> 4) * 16;
                    uint32_t vh[4];
                    ldsm4t(vh, a);
                    mma16816(o[np * 2],     ph, vh[0], vh[1]);
                    mma16816(o[np * 2 + 1], ph, vh[2], vh[3]);
                }
            }
        }
    }

    // ---- finalize: write fp16 hi/lo ctx in [B,L,D] ----
    l0 += __shfl_xor_sync(0xffffffffu, l0, 1);
    l0 += __shfl_xor_sync(0xffffffffu, l0, 2);
    l1 += __shfl_xor_sync(0xffffffffu, l1, 1);
    l1 += __shfl_xor_sync(0xffffffffu, l1, 2);
    float i0 = 1.f / l0, i1 = 1.f / l1;
    int qrow = qt * 128 + w * 16 + (lane >> 2);
    size_t r0 = (size_t)b * Lc + qrow;
#pragma unroll
    for (int nt = 0; nt < 8; nt++) {
        int cc = h * HDc + nt * 8 + (lane & 3) * 2;
#pragma unroll
        for (int rr = 0; rr < 2; rr++) {
            float va0 = (rr ? o[nt][2] * i1 : o[nt][0] * i0);
            float va1 = (rr ? o[nt][3] * i1 : o[nt][1] * i0);
            size_t idx = (r0 + rr * 8) * Dc + cc;
            uint32_t hi = packh2(va0, va1);
            __half2 hv = *(__half2*)&hi;
            *(uint32_t*)(g_CXh + idx) = hi;
            *(uint32_t*)(g_CXl + idx) =
                packh2(va0 - __half2float(hv.x), va1 - __half2float(hv.y));
        }
    }
}

// ---------------------------------------------------------------------------
extern "C" void kernel_launch(void* const* d_in, const int* in_sizes, int n_in,
                              void* d_out, int out_size) {
    const float* q  = (const float*)d_in[0];
    const float* k  = (const float*)d_in[1];
    const float* v  = (const float*)d_in[2];
    const float* Wq = (const float*)d_in[4];
    const float* bq = (const float*)d_in[5];
    const float* Wk = (const float*)d_in[6];
    const float* bk = (const float*)d_in[7];
    const float* Wv = (const float*)d_in[8];
    const float* bv = (const float*)d_in[9];
    const float* Wo = (const float*)d_in[10];
    const float* bo = (const float*)d_in[11];
    float* out = (float*)d_out;

    const int gsmem = 2 * 46080;          // 92160
    const int fsmem = 36864 + 3 * 18432;  // 92160
    cudaFuncSetAttribute(gemm_qkv, cudaFuncAttributeMaxDynamicSharedMemorySize, gsmem);
    cudaFuncSetAttribute(gemm_out, cudaFuncAttributeMaxDynamicSharedMemorySize, gsmem);
    cudaFuncSetAttribute(flash_mma, cudaFuncAttributeMaxDynamicSharedMemorySize, fsmem);

    const int nX4 = BL * Dc / 4;   // 1048576
    const int nW4 = Dc * Dc / 4;   // 65536

    dim3 grd_cw(nW4 / 256, 4);
    cvt_w<<<grd_cw, 256>>>((const float4*)Wq, (const float4*)Wk,
                           (const float4*)Wv, (const float4*)Wo);
    dim3 grd_ca(nX4 / 256, 3);
    cvt_act<<<grd_ca, 256>>>((const float4*)q, (const float4*)k, (const float4*)v);

    dim3 grd_qkv(Dc / 64, BL / 128, 3);
    gemm_qkv<<<grd_qkv, 256, gsmem>>>(bq, bk, bv);

    dim3 grd_fa(Lc / 128, Hc, Bc);     // 16 x 8 x 4
    flash_mma<<<grd_fa, 256, fsmem>>>();

    dim3 grd_o(Dc / 64, BL / 128);
    gemm_out<<<grd_o, 256, gsmem>>>(bo, out);
}

// round 17
// speedup vs baseline: 1.9400x; 1.0380x over previous
#include <cuda_runtime.h>
#include <cuda_fp16.h>
#include <math.h>
#include <stdint.h>

#define Bc 4
#define Lc 2048
#define Dc 512
#define Hc 8
#define HDc 64
#define BL (Bc*Lc)

// ---------------- scratch (device globals; no allocation allowed) ----------
__device__ __half g_Qh[Bc*Hc*Lc*HDc];
__device__ __half g_Ql[Bc*Hc*Lc*HDc];
__device__ __half g_K [Bc*Hc*Lc*HDc];
__device__ __half g_V [Bc*Hc*Lc*HDc];
__device__ __half g_CXh[BL*Dc];
__device__ __half g_CXl[BL*Dc];
__device__ __half g_A0h[BL*Dc];
__device__ __half g_A0l[BL*Dc];
__device__ __half g_A1h[BL*Dc];
__device__ __half g_A1l[BL*Dc];
__device__ __half g_A2h[BL*Dc];
__device__ __half g_A2l[BL*Dc];
__device__ __half g_Wh[4*Dc*Dc];

// ---------------- helpers ---------------------------------------------------
__device__ __forceinline__ uint32_t smem_u32(const void* p) {
    uint32_t a;
    asm("{ .reg .u64 t; cvta.to.shared.u64 t, %1; cvt.u32.u64 %0, t; }"
        : "=r"(a) : "l"(p));
    return a;
}
__device__ __forceinline__ void ldsm4(uint32_t* r, uint32_t addr) {
    asm volatile("ldmatrix.sync.aligned.m8n8.x4.shared.b16 {%0,%1,%2,%3}, [%4];"
                 : "=r"(r[0]), "=r"(r[1]), "=r"(r[2]), "=r"(r[3]) : "r"(addr));
}
__device__ __forceinline__ void ldsm4t(uint32_t* r, uint32_t addr) {
    asm volatile("ldmatrix.sync.aligned.m8n8.x4.trans.shared.b16 {%0,%1,%2,%3}, [%4];"
                 : "=r"(r[0]), "=r"(r[1]), "=r"(r[2]), "=r"(r[3]) : "r"(addr));
}
__device__ __forceinline__ void mma16816(float* d, const uint32_t* a,
                                         uint32_t b0, uint32_t b1) {
    asm volatile("mma.sync.aligned.m16n8k16.row.col.f32.f16.f16.f32 "
                 "{%0,%1,%2,%3}, {%4,%5,%6,%7}, {%8,%9}, {%0,%1,%2,%3};"
                 : "+f"(d[0]), "+f"(d[1]), "+f"(d[2]), "+f"(d[3])
                 : "r"(a[0]), "r"(a[1]), "r"(a[2]), "r"(a[3]), "r"(b0), "r"(b1));
}
__device__ __forceinline__ uint32_t packh2(float a, float b) {
    __half2 v = __floats2half2_rn(a, b);
    return *(uint32_t*)&v;
}
__device__ __forceinline__ float ex2(float x) {
    float r;
    asm("ex2.approx.f32 %0, %1;" : "=f"(r) : "f"(x));
    return r;
}
__device__ __forceinline__ void cpasync16(uint32_t s, const void* g) {
    asm volatile("cp.async.cg.shared.global [%0], [%1], 16;" :: "r"(s), "l"(g) : "memory");
}
__device__ __forceinline__ void cp_commit() {
    asm volatile("cp.async.commit_group;" ::: "memory");
}
__device__ __forceinline__ void cp_wait1() {
    asm volatile("cp.async.wait_group 1;" ::: "memory");
}

// ---------------------------------------------------------------------------
// Fused conversions (unchanged from R16).
// ---------------------------------------------------------------------------
__global__ void cvt_act(const float4* __restrict__ q, const float4* __restrict__ k,
                        const float4* __restrict__ v) {
    int i = blockIdx.x * blockDim.x + threadIdx.x;
    int y = blockIdx.y;
    const float4* src = (y == 0) ? q : (y == 1) ? k : v;
    uint2* hi = (uint2*)((y == 0) ? g_A0h : (y == 1) ? g_A1h : g_A2h);
    uint2* lo = (uint2*)((y == 0) ? g_A0l : (y == 1) ? g_A1l : g_A2l);
    float4 x = src[i];
    uint2 h, l;
    h.x = packh2(x.x, x.y); h.y = packh2(x.z, x.w);
    __half2 a = *(__half2*)&h.x, b = *(__half2*)&h.y;
    l.x = packh2(x.x - __half2float(a.x), x.y - __half2float(a.y));
    l.y = packh2(x.z - __half2float(b.x), x.w - __half2float(b.y));
    hi[i] = h; lo[i] = l;
}
__global__ void cvt_w(const float4* __restrict__ wq, const float4* __restrict__ wk,
                      const float4* __restrict__ wv, const float4* __restrict__ wo) {
    int i = blockIdx.x * blockDim.x + threadIdx.x;
    int y = blockIdx.y;
    const float4* src = (y == 0) ? wq : (y == 1) ? wk : (y == 2) ? wv : wo;
    float4 x = src[i];
    uint2 h;
    h.x = packh2(x.x, x.y); h.y = packh2(x.z, x.w);
    ((uint2*)(g_Wh + (size_t)y * Dc * Dc))[i] = h;
}

// ---------------------------------------------------------------------------
// Warp-MMA GEMM core: tile 128x128, BK=64, 2-pass (AhBh + AlBh), B single.
// Per ks: 8 LDSM -> 32 HMMA (density 4.0). cp.async double-buffered.
// Warp layout: wm = wid&3 (32-row band), wn = wid>>2 (64-col band).
// Accumulator d[2][8][4]. smem/stage 55296B, 2 stages.
// ---------------------------------------------------------------------------
#define GSTR 144  // smem row stride bytes (64 fp16 = 128B + 16 pad)
__device__ __forceinline__ void gemm_core(
    uint32_t sb, int t, int lane, int wm, int wn, int row0, int col0,
    const __half* Ah, const __half* Al, const __half* Bh,
    float d[2][8][4]) {
    const uint32_t SAL = 18432, SBH = 36864, STG = 55296;

    auto pf = [&](int kc, int st) {
        const int k0 = kc * 64;
        uint32_t dstb = sb + st * STG;
#pragma unroll
        for (int i = 0; i < 4; i++) {
            int idx = i * 256 + t, r = idx >> 3, c = idx & 7;
            size_t g = (size_t)(row0 + r) * 512 + k0 + c * 8;
            uint32_t d0 = dstb + r * GSTR + c * 16;
            cpasync16(d0,       Ah + g);
            cpasync16(d0 + SAL, Al + g);
        }
#pragma unroll
        for (int i = 0; i < 4; i++) {
            int idx = i * 256 + t, r = idx >> 3, c = idx & 7;
            size_t g = (size_t)(col0 + r) * 512 + k0 + c * 8;
            cpasync16(dstb + SBH + r * GSTR + c * 16, Bh + g);
        }
    };

    pf(0, 0); cp_commit();
    pf(1, 1); cp_commit();

    for (int c = 0; c < 8; c++) {
        cp_wait1();
        __syncthreads();
        const uint32_t stb = sb + (c & 1) * STG;
#pragma unroll
        for (int ks = 0; ks < 4; ks++) {
            uint32_t ah[2][4], al[2][4], bh[4][4];
            uint32_t aoff = (wm * 32 + (lane & 15)) * GSTR + ks * 32 + (lane >> 4) * 16;
            uint32_t boff = (wn * 64 + (lane & 15)) * GSTR + ks * 32 + (lane >> 4) * 16;
#pragma unroll
            for (int mt = 0; mt < 2; mt++) {
                ldsm4(ah[mt], stb + aoff + mt * 16 * GSTR);
                ldsm4(al[mt], stb + SAL + aoff + mt * 16 * GSTR);
            }
#pragma unroll
            for (int bp = 0; bp < 4; bp++)
                ldsm4(bh[bp], stb + SBH + boff + bp * 16 * GSTR);
#pragma unroll
            for (int mt = 0; mt < 2; mt++)
#pragma unroll
                for (int nt = 0; nt < 8; nt++) {
                    uint32_t h0 = bh[nt >> 1][nt & 1], h1 = bh[nt >> 1][(nt & 1) + 2];
                    mma16816(d[mt][nt], ah[mt], h0, h1);
                    mma16816(d[mt][nt], al[mt], h0, h1);
                }
        }
        __syncthreads();
        if (c + 2 < 8) pf(c + 2, c & 1);
        cp_commit();
    }
}

// ---------------------------------------------------------------------------
// Fused QKV projection: grid (4, 64, 3). Tile 128x128 (spans 2 heads).
// z==0 (Q): out fp16 hi/lo. z==1 (K), z==2 (V): out single fp16. [B,H,L,HD].
// ---------------------------------------------------------------------------
__global__ void __launch_bounds__(256, 2) gemm_qkv(
    const float* __restrict__ bq, const float* __restrict__ bk,
    const float* __restrict__ bv) {
    extern __shared__ char smem[];
    const uint32_t sb = smem_u32(smem);
    const int t = threadIdx.x, lane = t & 31, wid = t >> 5;
    const int wm = wid & 3, wn = wid >> 2;
    const int row0 = blockIdx.y * 128, col0 = blockIdx.x * 128;
    const int z = blockIdx.z;

    const __half* Ah = (z == 0) ? g_A0h : (z == 1) ? g_A1h : g_A2h;
    const __half* Al = (z == 0) ? g_A0l : (z == 1) ? g_A1l : g_A2l;
    const __half* Bh = g_Wh + (size_t)z * Dc * Dc;
    const float* bias = (z == 0) ? bq : (z == 1) ? bk : bv;
    __half* outh = (z == 0) ? g_Qh : (z == 1) ? g_K : g_V;

    float d[2][8][4];
#pragma unroll
    for (int i = 0; i < 2; i++)
#pragma unroll
        for (int j = 0; j < 8; j++)
#pragma unroll
            for (int e = 0; e < 4; e++) d[i][j][e] = 0.f;

    gemm_core(sb, t, lane, wm, wn, row0, col0, Ah, Al, Bh, d);

#pragma unroll
    for (int mt = 0; mt < 2; mt++) {
        int r1 = row0 + wm * 32 + mt * 16 + (lane >> 2);
#pragma unroll
        for (int nt = 0; nt < 8; nt++) {
            int cc = col0 + wn * 64 + nt * 8 + (lane & 3) * 2;
            float b0 = bias[cc], b1 = bias[cc + 1];
            float v00 = d[mt][nt][0] + b0, v01 = d[mt][nt][1] + b1;
            float v10 = d[mt][nt][2] + b0, v11 = d[mt][nt][3] + b1;
            int hh = cc >> 6, hd = cc & 63;
#pragma unroll
            for (int rr = 0; rr < 2; rr++) {
                int r = r1 + rr * 8;
                float va0 = rr ? v10 : v00, va1 = rr ? v11 : v01;
                int b = r >> 11, l = r & 2047;
                size_t idx = (((size_t)(b * Hc + hh)) * Lc + l) * HDc + hd;
                uint32_t hi = packh2(va0, va1);
                *(uint32_t*)(outh + idx) = hi;
                if (z == 0) {
                    __half2 hv = *(__half2*)&hi;
                    *(uint32_t*)(g_Ql + idx) =
                        packh2(va0 - __half2float(hv.x), va1 - __half2float(hv.y));
                }
            }
        }
    }
}

// ---------------------------------------------------------------------------
// Output projection: tile 128x128, A = ctx fp16 hi/lo, W single, out fp32.
// ---------------------------------------------------------------------------
__global__ void __launch_bounds__(256, 2) gemm_out(
    const float* __restrict__ bias, float* __restrict__ out) {
    extern __shared__ char smem[];
    const uint32_t sb = smem_u32(smem);
    const int t = threadIdx.x, lane = t & 31, wid = t >> 5;
    const int wm = wid & 3, wn = wid >> 2;
    const int row0 = blockIdx.y * 128, col0 = blockIdx.x * 128;

    float d[2][8][4];
#pragma unroll
    for (int i = 0; i < 2; i++)
#pragma unroll
        for (int j = 0; j < 8; j++)
#pragma unroll
            for (int e = 0; e < 4; e++) d[i][j][e] = 0.f;

    gemm_core(sb, t, lane, wm, wn, row0, col0, g_CXh, g_CXl, g_Wh + 3 * Dc * Dc, d);

#pragma unroll
    for (int mt = 0; mt < 2; mt++) {
        int r1 = row0 + wm * 32 + mt * 16 + (lane >> 2);
#pragma unroll
        for (int nt = 0; nt < 8; nt++) {
            int cc = col0 + wn * 64 + nt * 8 + (lane & 3) * 2;
            float b0 = bias[cc], b1 = bias[cc + 1];
            *(float2*)(out + (size_t)r1 * 512 + cc) =
                make_float2(d[mt][nt][0] + b0, d[mt][nt][1] + b1);
            *(float2*)(out + (size_t)(r1 + 8) * 512 + cc) =
                make_float2(d[mt][nt][2] + b0, d[mt][nt][3] + b1);
        }
    }
}

// ---------------------------------------------------------------------------
// Warp-MMA causal flash attention (unchanged from R16).
// ---------------------------------------------------------------------------
__global__ void __launch_bounds__(256, 2) flash_mma() {
    extern __shared__ char smem[];
    const uint32_t sb = smem_u32(smem);
    const int t = threadIdx.x, lane = t & 31, w = t >> 5;
    const int qt = 15 - blockIdx.x;  // heavy tiles first
    const int h = blockIdx.y, b = blockIdx.z;
    const size_t base = ((size_t)(b * Hc + h)) * Lc * HDc;
    const uint32_t SQH = 0, SQL = 18432;
    const uint32_t OV = 9216, STSZ = 18432, SST = 36864;

    const int njt = 2 * qt + 2;

    auto stage_base = [&](int jt) -> uint32_t {
        return sb + SST + (uint32_t)(jt % 3) * STSZ;
    };
    auto pf = [&](int jt) {
        uint32_t dstb = stage_base(jt);
#pragma unroll
        for (int i = 0; i < 2; i++) {
            int idx = i * 256 + t, r = idx >> 3, cb = (idx & 7) * 16, ce = (idx & 7) * 8;
            size_t g = base + (size_t)(jt * 64 + r) * HDc + ce;
            uint32_t d0 = dstb + r * GSTR + cb;
            cpasync16(d0,      g_K + g);
            cpasync16(d0 + OV, g_V + g);
        }
    };

    pf(0); cp_commit();
    pf(1); cp_commit();

#pragma unroll
    for (int i = 0; i < 4; i++) {
        int idx = i * 256 + t, r = idx >> 3, cb = (idx & 7) * 16, ce = (idx & 7) * 8;
        size_t g = base + (size_t)(qt * 128 + r) * HDc + ce;
        *(uint4*)(smem + SQH + r * GSTR + cb) = *(const uint4*)(g_Qh + g);
        *(uint4*)(smem + SQL + r * GSTR + cb) = *(const uint4*)(g_Ql + g);
    }
    __syncthreads();

    uint32_t qfh[4][4], qfl[4][4];
#pragma unroll
    for (int ks = 0; ks < 4; ks++) {
        uint32_t a = (w * 16 + (lane & 15)) * GSTR + ks * 32 + (lane >> 4) * 16;
        ldsm4(qfh[ks], sb + SQH + a);
        ldsm4(qfl[ks], sb + SQL + a);
    }

    float o[8][4];
#pragma unroll
    for (int i = 0; i < 8; i++)
#pragma unroll
        for (int e = 0; e < 4; e++) o[i][e] = 0.f;
    float m0 = -1e30f, m1 = -1e30f, l0 = 0.f, l1 = 0.f;
    const float SC2 = 0.125f * 1.44269504f;
    const int qlo = qt * 128 + w * 16;

    for (int jt = 0; jt < njt; jt++) {
        cp_wait1();
        __syncthreads();
        if (jt + 2 < njt) pf(jt + 2);
        cp_commit();

        const int J0 = jt * 64;
        const uint32_t stb = stage_base(jt);

        if (J0 <= qlo + 15) {
            float s[8][4];
#pragma unroll
            for (int i = 0; i < 8; i++)
#pragma unroll
                for (int e = 0; e < 4; e++) s[i][e] = 0.f;
#pragma unroll
            for (int ks = 0; ks < 4; ks++) {
#pragma unroll
                for (int bp = 0; bp < 4; bp++) {
                    if (J0 + bp * 16 > qlo + 15) continue;
                    uint32_t off = (bp * 16 + (lane & 15)) * GSTR + ks * 32 + (lane >> 4) * 16;
                    uint32_t kh[4];
                    ldsm4(kh, stb + off);
                    mma16816(s[bp * 2],     qfh[ks], kh[0], kh[2]);
                    mma16816(s[bp * 2 + 1], qfh[ks], kh[1], kh[3]);
                    mma16816(s[bp * 2],     qfl[ks], kh[0], kh[2]);
                    mma16816(s[bp * 2 + 1], qfl[ks], kh[1], kh[3]);
                }
            }

            if (J0 + 63 > qlo) {
                int q0 = qlo + (lane >> 2);
#pragma unroll
                for (int nt = 0; nt < 8; nt++) {
                    int kc = J0 + nt * 8 + (lane & 3) * 2;
                    s[nt][0] = (kc     <= q0)     ? s[nt][0] * SC2 : -1e30f;
                    s[nt][1] = (kc + 1 <= q0)     ? s[nt][1] * SC2 : -1e30f;
                    s[nt][2] = (kc     <= q0 + 8) ? s[nt][2] * SC2 : -1e30f;
                    s[nt][3] = (kc + 1 <= q0 + 8) ? s[nt][3] * SC2 : -1e30f;
                }
            } else {
#pragma unroll
                for (int nt = 0; nt < 8; nt++)
#pragma unroll
                    for (int e = 0; e < 4; e++) s[nt][e] *= SC2;
            }

            float a0 = -1e30f, a1 = -1e30f;
#pragma unroll
            for (int nt = 0; nt < 8; nt++) {
                a0 = fmaxf(a0, fmaxf(s[nt][0], s[nt][1]));
                a1 = fmaxf(a1, fmaxf(s[nt][2], s[nt][3]));
            }
            a0 = fmaxf(a0, __shfl_xor_sync(0xffffffffu, a0, 1));
            a0 = fmaxf(a0, __shfl_xor_sync(0xffffffffu, a0, 2));
            a1 = fmaxf(a1, __shfl_xor_sync(0xffffffffu, a1, 1));
            a1 = fmaxf(a1, __shfl_xor_sync(0xffffffffu, a1, 2));
            float n0 = fmaxf(m0, a0), n1 = fmaxf(m1, a1);
            bool upd = (n0 > m0) || (n1 > m1);
            if (__any_sync(0xffffffffu, upd)) {
                float c0 = ex2(m0 - n0), c1 = ex2(m1 - n1);
                m0 = n0; m1 = n1; l0 *= c0; l1 *= c1;
#pragma unroll
                for (int nt = 0; nt < 8; nt++) {
                    o[nt][0] *= c0; o[nt][1] *= c0; o[nt][2] *= c1; o[nt][3] *= c1;
                }
            }

#pragma unroll
            for (int ks = 0; ks < 4; ks++) {
                if (J0 + ks * 16 > qlo + 15) continue;
                float p[8];
                p[0] = ex2(s[2 * ks][0] - m0);     p[1] = ex2(s[2 * ks][1] - m0);
                p[2] = ex2(s[2 * ks][2] - m1);     p[3] = ex2(s[2 * ks][3] - m1);
                p[4] = ex2(s[2 * ks + 1][0] - m0); p[5] = ex2(s[2 * ks + 1][1] - m0);
                p[6] = ex2(s[2 * ks + 1][2] - m1); p[7] = ex2(s[2 * ks + 1][3] - m1);
                l0 += p[0] + p[1] + p[4] + p[5];
                l1 += p[2] + p[3] + p[6] + p[7];
                uint32_t ph[4];
                ph[0] = packh2(p[0], p[1]);
                ph[1] = packh2(p[2], p[3]);
                ph[2] = packh2(p[4], p[5]);
                ph[3] = packh2(p[6], p[7]);
#pragma unroll
                for (int np = 0; np < 4; np++) {
                    uint32_t a = stb + OV + (ks * 16 + (lane & 15)) * GSTR + np * 32 + (lane >> 4) * 16;
                    uint32_t vh[4];
                    ldsm4t(vh, a);
                    mma16816(o[np * 2],     ph, vh[0], vh[1]);
                    mma16816(o[np * 2 + 1], ph, vh[2], vh[3]);
                }
            }
        }
    }

    l0 += __shfl_xor_sync(0xffffffffu, l0, 1);
    l0 += __shfl_xor_sync(0xffffffffu, l0, 2);
    l1 += __shfl_xor_sync(0xffffffffu, l1, 1);
    l1 += __shfl_xor_sync(0xffffffffu, l1, 2);
    float i0 = 1.f / l0, i1 = 1.f / l1;
    int qrow = qt * 128 + w * 16 + (lane >> 2);
    size_t r0 = (size_t)b * Lc + qrow;
#pragma unroll
    for (int nt = 0; nt < 8; nt++) {
        int cc = h * HDc + nt * 8 + (lane & 3) * 2;
#pragma unroll
        for (int rr = 0; rr < 2; rr++) {
            float va0 = (rr ? o[nt][2] * i1 : o[nt][0] * i0);
            float va1 = (rr ? o[nt][3] * i1 : o[nt][1] * i0);
            size_t idx = (r0 + rr * 8) * Dc + cc;
            uint32_t hi = packh2(va0, va1);
            __half2 hv = *(__half2*)&hi;
            *(uint32_t*)(g_CXh + idx) = hi;
            *(uint32_t*)(g_CXl + idx) =
                packh2(va0 - __half2float(hv.x), va1 - __half2float(hv.y));
        }
    }
}

// ---------------------------------------------------------------------------
extern "C" void kernel_launch(void* const* d_in, const int* in_sizes, int n_in,
                              void* d_out, int out_size) {
    const float* q  = (const float*)d_in[0];
    const float* k  = (const float*)d_in[1];
    const float* v  = (const float*)d_in[2];
    const float* Wq = (const float*)d_in[4];
    const float* bq = (const float*)d_in[5];
    const float* Wk = (const float*)d_in[6];
    const float* bk = (const float*)d_in[7];
    const float* Wv = (const float*)d_in[8];
    const float* bv = (const float*)d_in[9];
    const float* Wo = (const float*)d_in[10];
    const float* bo = (const float*)d_in[11];
    float* out = (float*)d_out;

    const int gsmem = 2 * 55296;          // 110592
    const int fsmem = 36864 + 3 * 18432;  // 92160
    cudaFuncSetAttribute(gemm_qkv, cudaFuncAttributeMaxDynamicSharedMemorySize, gsmem);
    cudaFuncSetAttribute(gemm_out, cudaFuncAttributeMaxDynamicSharedMemorySize, gsmem);
    cudaFuncSetAttribute(flash_mma, cudaFuncAttributeMaxDynamicSharedMemorySize, fsmem);

    const int nX4 = BL * Dc / 4;   // 1048576
    const int nW4 = Dc * Dc / 4;   // 65536

    dim3 grd_cw(nW4 / 256, 4);
    cvt_w<<<grd_cw, 256>>>((const float4*)Wq, (const float4*)Wk,
                           (const float4*)Wv, (const float4*)Wo);
    dim3 grd_ca(nX4 / 256, 3);
    cvt_act<<<grd_ca, 256>>>((const float4*)q, (const float4*)k, (const float4*)v);

    dim3 grd_qkv(Dc / 128, BL / 128, 3);   // 4 x 64 x 3
    gemm_qkv<<<grd_qkv, 256, gsmem>>>(bq, bk, bv);

    dim3 grd_fa(Lc / 128, Hc, Bc);         // 16 x 8 x 4
    flash_mma<<<grd_fa, 256, fsmem>>>();

    dim3 grd_o(Dc / 128, BL / 128);        // 4 x 64
    gemm_out<<<grd_o, 256, gsmem>>>(bo, out);
}